// round 1
// baseline (speedup 1.0000x reference)
#include <cuda_runtime.h>

#define DD   1024
#define TT   2048
#define BB   2
#define MTOT (BB*TT)   // 4096
#define HH   16
#define DHD  64
#define RR   8

// Scratch (allocation-free rule: __device__ globals)
__device__ float g_Wq[DD*DD];
__device__ float g_Wv[DD*DD];
__device__ float g_Q [MTOT*DD];
__device__ float g_K [MTOT*DD];
__device__ float g_V [MTOT*DD];
__device__ float g_AO[MTOT*DD];

// W_eff[o][c] = w[o][c] + 2 * sum_r Bm[o][r] * A[r][c]
__global__ void fold_kernel(const float* __restrict__ w, const float* __restrict__ A,
                            const float* __restrict__ Bm, float* __restrict__ Weff) {
    int i = blockIdx.x * blockDim.x + threadIdx.x;
    if (i >= DD*DD) return;
    int o = i >> 10, c = i & 1023;
    float acc = w[i];
#pragma unroll
    for (int r = 0; r < RR; r++)
        acc += 2.0f * Bm[o*RR + r] * A[r*DD + c];
    Weff[i] = acc;
}

// C[M,N] = A[M,K] @ W[N,K]^T, all row-major, M%64==0, N%64==0, K%16==0
// 64x64 tile, Bk=16, 256 threads, 4x4 per thread
__global__ __launch_bounds__(256) void gemm_abt(
        const float* __restrict__ Am, const float* __restrict__ Wm,
        float* __restrict__ Cm, int M, int N, int K) {
    __shared__ __align__(16) float As[16][68];
    __shared__ __align__(16) float Ws[16][68];
    int tx = threadIdx.x & 15, ty = threadIdx.x >> 4;
    int m0 = blockIdx.y * 64, n0 = blockIdx.x * 64;
    float c[4][4] = {};
    for (int k0 = 0; k0 < K; k0 += 16) {
#pragma unroll
        for (int s = 0; s < 4; s++) {
            int idx = (int)threadIdx.x + s*256;
            int mm = idx >> 4, kk = idx & 15;
            As[kk][mm] = Am[(size_t)(m0+mm)*K + k0 + kk];
            Ws[kk][mm] = Wm[(size_t)(n0+mm)*K + k0 + kk];
        }
        __syncthreads();
#pragma unroll
        for (int kk = 0; kk < 16; kk++) {
            float4 a = *(const float4*)&As[kk][ty*4];
            float4 b = *(const float4*)&Ws[kk][tx*4];
            c[0][0] += a.x*b.x; c[0][1] += a.x*b.y; c[0][2] += a.x*b.z; c[0][3] += a.x*b.w;
            c[1][0] += a.y*b.x; c[1][1] += a.y*b.y; c[1][2] += a.y*b.z; c[1][3] += a.y*b.w;
            c[2][0] += a.z*b.x; c[2][1] += a.z*b.y; c[2][2] += a.z*b.z; c[2][3] += a.z*b.w;
            c[3][0] += a.w*b.x; c[3][1] += a.w*b.y; c[3][2] += a.w*b.z; c[3][3] += a.w*b.w;
        }
        __syncthreads();
    }
#pragma unroll
    for (int i = 0; i < 4; i++) {
        float4 v = make_float4(c[i][0], c[i][1], c[i][2], c[i][3]);
        *(float4*)&Cm[(size_t)(m0 + ty*4 + i)*N + n0 + tx*4] = v;
    }
}

// Causal flash attention, fp32. One block = one (b,h) x one 64-row q tile.
// 64 threads; each thread owns one q row (q and o accumulators in registers).
__global__ __launch_bounds__(64) void flash_kernel(
        const float* __restrict__ Q, const float* __restrict__ K,
        const float* __restrict__ V, float* __restrict__ O) {
    __shared__ __align__(16) float Ks[64][64];
    __shared__ __align__(16) float Vs[64][64];
    __shared__ float Ss[64][64];   // [j][r] : thread r's column — conflict-free
    int qt = blockIdx.x;
    int bh = blockIdx.y;
    int b = bh >> 4, h = bh & 15;
    int r = threadIdx.x;
    int qg = qt*64 + r;

    const float* qptr = Q + ((size_t)(b*TT + qg))*DD + h*DHD;
    float q[64];
#pragma unroll
    for (int i = 0; i < 16; i++) {
        float4 t = *(const float4*)(qptr + 4*i);
        q[4*i+0]=t.x; q[4*i+1]=t.y; q[4*i+2]=t.z; q[4*i+3]=t.w;
    }
    float o[64];
#pragma unroll
    for (int d = 0; d < 64; d++) o[d] = 0.0f;
    float m = -1e30f, l = 0.0f;

    for (int kt = 0; kt <= qt; kt++) {
        // cooperative load of K,V tiles: 64 rows x 16 float4, coalesced
#pragma unroll
        for (int s = 0; s < 16; s++) {
            int idx = r + s*64;          // 0..1023
            int row = idx >> 4, c4 = idx & 15;
            size_t base = ((size_t)(b*TT + kt*64 + row))*DD + h*DHD + c4*4;
            *(float4*)&Ks[row][c4*4] = *(const float4*)(K + base);
            *(float4*)&Vs[row][c4*4] = *(const float4*)(V + base);
        }
        __syncthreads();

        float mt = -1e30f;
        bool diag = (kt == qt);
        for (int j = 0; j < 64; j++) {
            float s = 0.0f;
#pragma unroll
            for (int i = 0; i < 16; i++) {
                float4 kv = *(const float4*)&Ks[j][4*i];
                s += q[4*i+0]*kv.x + q[4*i+1]*kv.y + q[4*i+2]*kv.z + q[4*i+3]*kv.w;
            }
            s *= 0.125f;   // 1/sqrt(64)
            if (diag && (kt*64 + j > qg)) s = -1e30f;
            Ss[j][r] = s;
            mt = fmaxf(mt, s);
        }
        float mnew = fmaxf(m, mt);
        float corr = __expf(m - mnew);
        l *= corr;
#pragma unroll
        for (int d = 0; d < 64; d++) o[d] *= corr;

        for (int j = 0; j < 64; j++) {
            float p = __expf(Ss[j][r] - mnew);
            l += p;
#pragma unroll
            for (int i = 0; i < 16; i++) {
                float4 vv = *(const float4*)&Vs[j][4*i];
                o[4*i+0] += p*vv.x; o[4*i+1] += p*vv.y;
                o[4*i+2] += p*vv.z; o[4*i+3] += p*vv.w;
            }
        }
        m = mnew;
        __syncthreads();
    }

    float inv = 1.0f / l;
    float* op = O + ((size_t)(b*TT + qg))*DD + h*DHD;
#pragma unroll
    for (int i = 0; i < 16; i++) {
        float4 t = make_float4(o[4*i+0]*inv, o[4*i+1]*inv, o[4*i+2]*inv, o[4*i+3]*inv);
        *(float4*)(op + 4*i) = t;
    }
}

extern "C" void kernel_launch(void* const* d_in, const int* in_sizes, int n_in,
                              void* d_out, int out_size) {
    const float* x    = (const float*)d_in[0];
    // d_in[1] = attn_mask (bool) — causal, structure known, unused
    const float* wq_w = (const float*)d_in[2];
    const float* wq_A = (const float*)d_in[3];
    const float* wq_B = (const float*)d_in[4];
    const float* wk_w = (const float*)d_in[5];
    const float* wv_w = (const float*)d_in[6];
    const float* wv_A = (const float*)d_in[7];
    const float* wv_B = (const float*)d_in[8];
    const float* wo_w = (const float*)d_in[9];
    float* out = (float*)d_out;

    float *Wq, *Wv, *Qb, *Kb, *Vb, *AO;
    cudaGetSymbolAddress((void**)&Wq, g_Wq);
    cudaGetSymbolAddress((void**)&Wv, g_Wv);
    cudaGetSymbolAddress((void**)&Qb, g_Q);
    cudaGetSymbolAddress((void**)&Kb, g_K);
    cudaGetSymbolAddress((void**)&Vb, g_V);
    cudaGetSymbolAddress((void**)&AO, g_AO);

    fold_kernel<<<(DD*DD + 255)/256, 256>>>(wq_w, wq_A, wq_B, Wq);
    fold_kernel<<<(DD*DD + 255)/256, 256>>>(wv_w, wv_A, wv_B, Wv);

    dim3 gg(DD/64, MTOT/64);   // (16, 64)
    gemm_abt<<<gg, 256>>>(x,  Wq,   Qb,  MTOT, DD, DD);
    gemm_abt<<<gg, 256>>>(x,  wk_w, Kb,  MTOT, DD, DD);
    gemm_abt<<<gg, 256>>>(x,  Wv,   Vb,  MTOT, DD, DD);

    flash_kernel<<<dim3(TT/64, BB*HH), 64>>>(Qb, Kb, Vb, AO);

    gemm_abt<<<gg, 256>>>(AO, wo_w, out, MTOT, DD, DD);
}

// round 3
// speedup vs baseline: 1.4760x; 1.4760x over previous
#include <cuda_runtime.h>
#include <cuda_bf16.h>
#include <cstdint>

#define DD    1024
#define TT    2048
#define BB    2
#define MTOT  4096
#define HH    16
#define DHD   64
#define RR    8
#define NQKV  3072

// ---- mma.sync GEMM tiling ----
#define TM 128
#define TN 128
#define KSTEP 32                    // bf16 elems per k-chunk
#define NK (DD / KSTEP)             // 32
#define ROWB 80                     // padded row stride bytes (64B data + 16B pad)
#define TILE_BYTES (128 * ROWB)     // 10240
#define STAGE_BYTES (4 * TILE_BYTES) // Ah, Al, Bh, Bl
#define SMEM_TOTAL (2 * STAGE_BYTES) // 81920

// ---- scratch (__device__ globals; no allocs allowed) ----
__device__ __nv_bfloat16 g_Xh [MTOT * DD];
__device__ __nv_bfloat16 g_Xl [MTOT * DD];
__device__ __nv_bfloat16 g_Wh [NQKV * DD];
__device__ __nv_bfloat16 g_Wl [NQKV * DD];
__device__ __nv_bfloat16 g_WOh[DD * DD];
__device__ __nv_bfloat16 g_WOl[DD * DD];
__device__ float         g_QKV[(size_t)MTOT * NQKV];
__device__ float         g_AO [MTOT * DD];
__device__ __nv_bfloat16 g_AOh[MTOT * DD];
__device__ __nv_bfloat16 g_AOl[MTOT * DD];

// ---------------- PTX helpers (all sm_80/90 portable) ----------------
__device__ __forceinline__ uint32_t smem_u32(const void* p) {
    uint32_t a;
    asm("{ .reg .u64 t; cvta.to.shared.u64 t, %1; cvt.u32.u64 %0, t; }" : "=r"(a) : "l"(p));
    return a;
}
#define CP_ASYNC16(dst, src) \
    asm volatile("cp.async.cg.shared.global [%0], [%1], 16;" :: "r"(dst), "l"(src))
#define CP_COMMIT()   asm volatile("cp.async.commit_group;" ::: "memory")
#define CP_WAIT(n)    asm volatile("cp.async.wait_group %0;" :: "n"(n) : "memory")

__device__ __forceinline__ void ldsm4(uint32_t* r, uint32_t addr) {
    asm volatile("ldmatrix.sync.aligned.m8n8.x4.shared.b16 {%0,%1,%2,%3}, [%4];"
                 : "=r"(r[0]), "=r"(r[1]), "=r"(r[2]), "=r"(r[3]) : "r"(addr));
}
__device__ __forceinline__ void mma16816(float* c, const uint32_t* a, const uint32_t* b) {
    asm volatile("mma.sync.aligned.m16n8k16.row.col.f32.bf16.bf16.f32 "
                 "{%0,%1,%2,%3}, {%4,%5,%6,%7}, {%8,%9}, {%0,%1,%2,%3};"
                 : "+f"(c[0]), "+f"(c[1]), "+f"(c[2]), "+f"(c[3])
                 : "r"(a[0]), "r"(a[1]), "r"(a[2]), "r"(a[3]), "r"(b[0]), "r"(b[1]));
}

// ---------------- prep kernels ----------------
__global__ void split_kernel(const float* __restrict__ s, __nv_bfloat16* __restrict__ h,
                             __nv_bfloat16* __restrict__ l, int n) {
    int i = blockIdx.x * blockDim.x + threadIdx.x;
    if (i >= n) return;
    float v = s[i];
    __nv_bfloat16 hb = __float2bfloat16(v);
    float r = v - __bfloat162float(hb);
    h[i] = hb;
    l[i] = __float2bfloat16(r);
}

// builds [3072,1024] concat weight = [Wq_eff ; Wk ; Wv_eff], split into hi/lo
__global__ void prep_wcat(const float* __restrict__ wq, const float* __restrict__ qA,
                          const float* __restrict__ qB, const float* __restrict__ wk,
                          const float* __restrict__ wv, const float* __restrict__ vA,
                          const float* __restrict__ vB,
                          __nv_bfloat16* __restrict__ Wh, __nv_bfloat16* __restrict__ Wl) {
    int i = blockIdx.x * blockDim.x + threadIdx.x;
    if (i >= NQKV * DD) return;
    int o = i / DD, c = i % DD;
    float v;
    if (o < 1024) {
        v = wq[o * DD + c];
#pragma unroll
        for (int r = 0; r < RR; r++) v += 2.0f * qB[o * RR + r] * qA[r * DD + c];
    } else if (o < 2048) {
        v = wk[(o - 1024) * DD + c];
    } else {
        int oo = o - 2048;
        v = wv[oo * DD + c];
#pragma unroll
        for (int r = 0; r < RR; r++) v += 2.0f * vB[oo * RR + r] * vA[r * DD + c];
    }
    __nv_bfloat16 hb = __float2bfloat16(v);
    float rr = v - __bfloat162float(hb);
    Wh[i] = hb;
    Wl[i] = __float2bfloat16(rr);
}

// ---------------- mma.sync split-bf16 GEMM ----------------
// C[M, Ntot] = A[M,1024] @ B[Ntot,1024]^T via Ah.Bh + Ah.Bl + Al.Bh
__device__ __forceinline__ void load_stage(
    uint32_t stage_base,
    const __nv_bfloat16* __restrict__ Ah, const __nv_bfloat16* __restrict__ Al,
    const __nv_bfloat16* __restrict__ Bh, const __nv_bfloat16* __restrict__ Bl,
    int m0, int n0, int kc, int tid)
{
    const __nv_bfloat16* srcs[4] = {Ah, Al, Bh, Bl};
#pragma unroll
    for (int t = 0; t < 4; t++) {
        const __nv_bfloat16* base = srcs[t] + (size_t)(t < 2 ? m0 : n0) * DD + kc * KSTEP;
        uint32_t dst_tile = stage_base + t * TILE_BYTES;
#pragma unroll
        for (int i = 0; i < 2; i++) {
            int idx = tid + i * 256;          // 0..511
            int row = idx >> 2, c = idx & 3;  // 128 rows x 4 x 16B
            CP_ASYNC16(dst_tile + row * ROWB + c * 16,
                       (const char*)(base + (size_t)row * DD) + c * 16);
        }
    }
}

__global__ __launch_bounds__(256) void gemm_ts(
    const __nv_bfloat16* __restrict__ Ah, const __nv_bfloat16* __restrict__ Al,
    const __nv_bfloat16* __restrict__ Bh, const __nv_bfloat16* __restrict__ Bl,
    float* __restrict__ C, int Ntot)
{
    extern __shared__ char smem[];
    uint32_t sb = smem_u32(smem);
    int tid = threadIdx.x;
    int wid = tid >> 5, lane = tid & 31;
    int wm = (wid & 3) * 32;      // warp M offset within tile
    int wn = (wid >> 2) * 64;     // warp N offset within tile
    int m0 = blockIdx.y * TM, n0 = blockIdx.x * TN;

    // per-lane ldmatrix offsets (within a tile)
    uint32_t aoff = (uint32_t)(wm + (lane & 15)) * ROWB + (lane >> 4) * 16;
    uint32_t boff = (uint32_t)(wn + (lane & 7) + ((lane >> 4) << 3)) * ROWB
                  + ((lane >> 3) & 1) * 16;

    float acc[2][8][4];
#pragma unroll
    for (int i = 0; i < 2; i++)
#pragma unroll
        for (int j = 0; j < 8; j++)
#pragma unroll
            for (int k = 0; k < 4; k++) acc[i][j][k] = 0.0f;

    // prologue: two stages in flight
    load_stage(sb, Ah, Al, Bh, Bl, m0, n0, 0, tid);
    CP_COMMIT();
    load_stage(sb + STAGE_BYTES, Ah, Al, Bh, Bl, m0, n0, 1, tid);
    CP_COMMIT();

    for (int c = 0; c < NK; c++) {
        uint32_t st = sb + (c & 1) * STAGE_BYTES;
        if (c + 2 < NK) { CP_WAIT(1); } else { CP_WAIT(0); }
        __syncthreads();

        uint32_t baseAh = st + aoff;
        uint32_t baseAl = baseAh + TILE_BYTES;
        uint32_t baseBh = st + 2 * TILE_BYTES + boff;
        uint32_t baseBl = baseBh + TILE_BYTES;

#pragma unroll
        for (int kk = 0; kk < 2; kk++) {     // two k16 halves of the k32 chunk
            uint32_t koff = kk * 32;
            uint32_t ah[2][4], al[2][4], bh[4][4], bl[4][4];
#pragma unroll
            for (int mt = 0; mt < 2; mt++) {
                ldsm4(ah[mt], baseAh + mt * 16 * ROWB + koff);
                ldsm4(al[mt], baseAl + mt * 16 * ROWB + koff);
            }
#pragma unroll
            for (int np = 0; np < 4; np++) {
                ldsm4(bh[np], baseBh + np * 16 * ROWB + koff);
                ldsm4(bl[np], baseBl + np * 16 * ROWB + koff);
            }
#pragma unroll
            for (int mt = 0; mt < 2; mt++)
#pragma unroll
                for (int np = 0; np < 4; np++) {
                    mma16816(acc[mt][np*2],   ah[mt], &bh[np][0]);
                    mma16816(acc[mt][np*2],   ah[mt], &bl[np][0]);
                    mma16816(acc[mt][np*2],   al[mt], &bh[np][0]);
                    mma16816(acc[mt][np*2+1], ah[mt], &bh[np][2]);
                    mma16816(acc[mt][np*2+1], ah[mt], &bl[np][2]);
                    mma16816(acc[mt][np*2+1], al[mt], &bh[np][2]);
                }
        }
        __syncthreads();   // all smem reads for this stage done
        if (c + 2 < NK) {
            load_stage(st, Ah, Al, Bh, Bl, m0, n0, c + 2, tid);
            CP_COMMIT();
        }
    }

    // epilogue: write fp32 C
    int rbase = m0 + wm + (lane >> 2);
    int cbase = n0 + wn + 2 * (lane & 3);
#pragma unroll
    for (int mt = 0; mt < 2; mt++)
#pragma unroll
        for (int nt = 0; nt < 8; nt++) {
            float* p0 = C + (size_t)(rbase + mt * 16) * Ntot + cbase + nt * 8;
            float* p1 = C + (size_t)(rbase + mt * 16 + 8) * Ntot + cbase + nt * 8;
            *(float2*)p0 = make_float2(acc[mt][nt][0], acc[mt][nt][1]);
            *(float2*)p1 = make_float2(acc[mt][nt][2], acc[mt][nt][3]);
        }
}

// ---------------- causal flash attention (fp32, SIMT) ----------------
// QKV layout: [B*T, 3072], Q at col h*64, K at 1024+h*64, V at 2048+h*64
__global__ __launch_bounds__(64) void flash_kernel(
        const float* __restrict__ QKV, float* __restrict__ O) {
    __shared__ __align__(16) float Ks[64][64];
    __shared__ __align__(16) float Vs[64][64];
    __shared__ float Ss[64][64];
    int qt = blockIdx.x;
    int bh = blockIdx.y;
    int b = bh >> 4, h = bh & 15;
    int r = threadIdx.x;
    int qg = qt * 64 + r;

    const float* qptr = QKV + (size_t)(b * TT + qg) * NQKV + h * DHD;
    float q[64];
#pragma unroll
    for (int i = 0; i < 16; i++) {
        float4 t = *(const float4*)(qptr + 4 * i);
        q[4*i+0]=t.x; q[4*i+1]=t.y; q[4*i+2]=t.z; q[4*i+3]=t.w;
    }
    float o[64];
#pragma unroll
    for (int d = 0; d < 64; d++) o[d] = 0.0f;
    float m = -1e30f, l = 0.0f;

    for (int kt = 0; kt <= qt; kt++) {
#pragma unroll
        for (int s = 0; s < 16; s++) {
            int idx = r + s * 64;
            int row = idx >> 4, c4 = idx & 15;
            size_t base = (size_t)(b * TT + kt * 64 + row) * NQKV + h * DHD + c4 * 4;
            *(float4*)&Ks[row][c4*4] = *(const float4*)(QKV + base + 1024);
            *(float4*)&Vs[row][c4*4] = *(const float4*)(QKV + base + 2048);
        }
        __syncthreads();

        float mt = -1e30f;
        bool diag = (kt == qt);
        for (int j = 0; j < 64; j++) {
            float s = 0.0f;
#pragma unroll
            for (int i = 0; i < 16; i++) {
                float4 kv = *(const float4*)&Ks[j][4*i];
                s += q[4*i+0]*kv.x + q[4*i+1]*kv.y + q[4*i+2]*kv.z + q[4*i+3]*kv.w;
            }
            s *= 0.125f;
            if (diag && (kt * 64 + j > qg)) s = -1e30f;
            Ss[j][r] = s;
            mt = fmaxf(mt, s);
        }
        float mnew = fmaxf(m, mt);
        float corr = __expf(m - mnew);
        l *= corr;
#pragma unroll
        for (int d = 0; d < 64; d++) o[d] *= corr;

        for (int j = 0; j < 64; j++) {
            float p = __expf(Ss[j][r] - mnew);
            l += p;
#pragma unroll
            for (int i = 0; i < 16; i++) {
                float4 vv = *(const float4*)&Vs[j][4*i];
                o[4*i+0] += p*vv.x; o[4*i+1] += p*vv.y;
                o[4*i+2] += p*vv.z; o[4*i+3] += p*vv.w;
            }
        }
        m = mnew;
        __syncthreads();
    }

    float inv = 1.0f / l;
    float* op = O + (size_t)(b * TT + qg) * DD + h * DHD;
#pragma unroll
    for (int i = 0; i < 16; i++) {
        float4 t = make_float4(o[4*i+0]*inv, o[4*i+1]*inv, o[4*i+2]*inv, o[4*i+3]*inv);
        *(float4*)(op + 4 * i) = t;
    }
}

// ---------------- launch ----------------
extern "C" void kernel_launch(void* const* d_in, const int* in_sizes, int n_in,
                              void* d_out, int out_size) {
    const float* x    = (const float*)d_in[0];
    const float* wq_w = (const float*)d_in[2];
    const float* wq_A = (const float*)d_in[3];
    const float* wq_B = (const float*)d_in[4];
    const float* wk_w = (const float*)d_in[5];
    const float* wv_w = (const float*)d_in[6];
    const float* wv_A = (const float*)d_in[7];
    const float* wv_B = (const float*)d_in[8];
    const float* wo_w = (const float*)d_in[9];
    float* out = (float*)d_out;

    static bool attr_set = false;
    if (!attr_set) {
        cudaFuncSetAttribute(gemm_ts, cudaFuncAttributeMaxDynamicSharedMemorySize, SMEM_TOTAL);
        attr_set = true;
    }

    __nv_bfloat16 *Xh, *Xl, *Wh, *Wl, *WOh, *WOl, *AOh, *AOl;
    float *QKV, *AO;
    cudaGetSymbolAddress((void**)&Xh,  g_Xh);
    cudaGetSymbolAddress((void**)&Xl,  g_Xl);
    cudaGetSymbolAddress((void**)&Wh,  g_Wh);
    cudaGetSymbolAddress((void**)&Wl,  g_Wl);
    cudaGetSymbolAddress((void**)&WOh, g_WOh);
    cudaGetSymbolAddress((void**)&WOl, g_WOl);
    cudaGetSymbolAddress((void**)&AOh, g_AOh);
    cudaGetSymbolAddress((void**)&AOl, g_AOl);
    cudaGetSymbolAddress((void**)&QKV, g_QKV);
    cudaGetSymbolAddress((void**)&AO,  g_AO);

    split_kernel<<<(MTOT * DD) / 256, 256>>>(x, Xh, Xl, MTOT * DD);
    prep_wcat<<<(NQKV * DD) / 256, 256>>>(wq_w, wq_A, wq_B, wk_w, wv_w, wv_A, wv_B, Wh, Wl);
    split_kernel<<<(DD * DD) / 256, 256>>>(wo_w, WOh, WOl, DD * DD);

    gemm_ts<<<dim3(NQKV / TN, MTOT / TM), 256, SMEM_TOTAL>>>(Xh, Xl, Wh, Wl, QKV, NQKV);

    flash_kernel<<<dim3(TT / 64, BB * HH), 64>>>(QKV, AO);

    split_kernel<<<(MTOT * DD) / 256, 256>>>(AO, AOh, AOl, MTOT * DD);
    gemm_ts<<<dim3(DD / TN, MTOT / TM), 256, SMEM_TOTAL>>>(AOh, AOl, WOh, WOl, out, DD);
}

// round 4
// speedup vs baseline: 3.2352x; 2.1919x over previous
#include <cuda_runtime.h>
#include <cuda_bf16.h>
#include <cstdint>

#define DD    1024
#define TT    2048
#define BB    2
#define MTOT  4096
#define HH    16
#define DHD   64
#define RR    8
#define NQKV  3072

// ---- mma.sync GEMM tiling ----
#define TM 128
#define TN 128
#define KSTEP 32
#define NK (DD / KSTEP)             // 32
#define ROWB 80
#define TILE_BYTES (128 * ROWB)
#define STAGE_BYTES (4 * TILE_BYTES)
#define SMEM_TOTAL (2 * STAGE_BYTES)

// ---- flash tiling ----
#define FROWB 144                   // 128B data + 16B pad
#define FTILE (64 * FROWB)          // 9216
#define FSTAGE (4 * FTILE)          // 36864  (Kh,Kl,Vh,Vl)
#define FSMEM (2 * FSTAGE)          // 73728

// ---- scratch ----
__device__ __nv_bfloat16 g_Xh [MTOT * DD];
__device__ __nv_bfloat16 g_Xl [MTOT * DD];
__device__ __nv_bfloat16 g_Wh [NQKV * DD];
__device__ __nv_bfloat16 g_Wl [NQKV * DD];
__device__ __nv_bfloat16 g_WOh[DD * DD];
__device__ __nv_bfloat16 g_WOl[DD * DD];
__device__ float         g_QKV[(size_t)MTOT * NQKV];
__device__ __nv_bfloat16 g_Qh [MTOT * DD];
__device__ __nv_bfloat16 g_Ql [MTOT * DD];
__device__ __nv_bfloat16 g_Kh [MTOT * DD];
__device__ __nv_bfloat16 g_Kl [MTOT * DD];
__device__ __nv_bfloat16 g_Vth[MTOT * DD];
__device__ __nv_bfloat16 g_Vtl[MTOT * DD];
__device__ __nv_bfloat16 g_AOh[MTOT * DD];
__device__ __nv_bfloat16 g_AOl[MTOT * DD];

// ---------------- PTX helpers ----------------
__device__ __forceinline__ uint32_t smem_u32(const void* p) {
    uint32_t a;
    asm("{ .reg .u64 t; cvta.to.shared.u64 t, %1; cvt.u32.u64 %0, t; }" : "=r"(a) : "l"(p));
    return a;
}
#define CP_ASYNC16(dst, src) \
    asm volatile("cp.async.cg.shared.global [%0], [%1], 16;" :: "r"(dst), "l"(src))
#define CP_COMMIT()   asm volatile("cp.async.commit_group;" ::: "memory")
#define CP_WAIT(n)    asm volatile("cp.async.wait_group %0;" :: "n"(n) : "memory")

__device__ __forceinline__ void ldsm4(uint32_t* r, uint32_t addr) {
    asm volatile("ldmatrix.sync.aligned.m8n8.x4.shared.b16 {%0,%1,%2,%3}, [%4];"
                 : "=r"(r[0]), "=r"(r[1]), "=r"(r[2]), "=r"(r[3]) : "r"(addr));
}
__device__ __forceinline__ void mma16816(float* c, const uint32_t* a, const uint32_t* b) {
    asm volatile("mma.sync.aligned.m16n8k16.row.col.f32.bf16.bf16.f32 "
                 "{%0,%1,%2,%3}, {%4,%5,%6,%7}, {%8,%9}, {%0,%1,%2,%3};"
                 : "+f"(c[0]), "+f"(c[1]), "+f"(c[2]), "+f"(c[3])
                 : "r"(a[0]), "r"(a[1]), "r"(a[2]), "r"(a[3]), "r"(b[0]), "r"(b[1]));
}

// ---------------- prep kernels ----------------
__global__ void split_kernel(const float* __restrict__ s, __nv_bfloat16* __restrict__ h,
                             __nv_bfloat16* __restrict__ l, int n) {
    int i = blockIdx.x * blockDim.x + threadIdx.x;
    if (i >= n) return;
    float v = s[i];
    __nv_bfloat16 hb = __float2bfloat16(v);
    h[i] = hb;
    l[i] = __float2bfloat16(v - __bfloat162float(hb));
}

__global__ void prep_wcat(const float* __restrict__ wq, const float* __restrict__ qA,
                          const float* __restrict__ qB, const float* __restrict__ wk,
                          const float* __restrict__ wv, const float* __restrict__ vA,
                          const float* __restrict__ vB,
                          __nv_bfloat16* __restrict__ Wh, __nv_bfloat16* __restrict__ Wl) {
    int i = blockIdx.x * blockDim.x + threadIdx.x;
    if (i >= NQKV * DD) return;
    int o = i / DD, c = i % DD;
    float v;
    if (o < 1024) {
        v = wq[o * DD + c];
#pragma unroll
        for (int r = 0; r < RR; r++) v += 2.0f * qB[o * RR + r] * qA[r * DD + c];
    } else if (o < 2048) {
        v = wk[(o - 1024) * DD + c];
    } else {
        int oo = o - 2048;
        v = wv[oo * DD + c];
#pragma unroll
        for (int r = 0; r < RR; r++) v += 2.0f * vB[oo * RR + r] * vA[r * DD + c];
    }
    __nv_bfloat16 hb = __float2bfloat16(v);
    Wh[i] = hb;
    Wl[i] = __float2bfloat16(v - __bfloat162float(hb));
}

// QKV fp32 [b*T][3072] -> split bf16 per-head layouts.
// Qh/Ql, Kh/Kl: [bh][t][64]; Vth/Vtl: [bh][d][t] (transposed via smem).
__global__ __launch_bounds__(256) void convert_qkv(
    const float* __restrict__ QKV,
    __nv_bfloat16* __restrict__ Qh, __nv_bfloat16* __restrict__ Ql,
    __nv_bfloat16* __restrict__ Kh, __nv_bfloat16* __restrict__ Kl,
    __nv_bfloat16* __restrict__ Vth, __nv_bfloat16* __restrict__ Vtl)
{
    __shared__ float vs[64][65];
    int tb = blockIdx.x;           // 0..31 t-tile
    int bh = blockIdx.y;           // 0..31
    int b = bh >> 4, h = bh & 15;
    int t0 = tb * 64;
    int tid = threadIdx.x;
#pragma unroll
    for (int i = 0; i < 16; i++) {
        int idx = tid + i * 256;            // 0..4095
        int t = idx >> 6, d = idx & 63;
        size_t src = (size_t)(b * TT + t0 + t) * NQKV + h * DHD + d;
        size_t dst = (size_t)(bh * TT + t0 + t) * DHD + d;
        float qv = QKV[src] * 0.125f;       // fold 1/sqrt(dh)
        __nv_bfloat16 qhh = __float2bfloat16(qv);
        Qh[dst] = qhh;
        Ql[dst] = __float2bfloat16(qv - __bfloat162float(qhh));
        float kv = QKV[src + 1024];
        __nv_bfloat16 khh = __float2bfloat16(kv);
        Kh[dst] = khh;
        Kl[dst] = __float2bfloat16(kv - __bfloat162float(khh));
        vs[t][d] = QKV[src + 2048];
    }
    __syncthreads();
#pragma unroll
    for (int i = 0; i < 16; i++) {
        int idx = tid + i * 256;
        int d = idx >> 6, t = idx & 63;
        float vv = vs[t][d];
        __nv_bfloat16 vhh = __float2bfloat16(vv);
        size_t dst = (size_t)(bh * DHD + d) * TT + t0 + t;
        Vth[dst] = vhh;
        Vtl[dst] = __float2bfloat16(vv - __bfloat162float(vhh));
    }
}

// ---------------- mma.sync split-bf16 GEMM (unchanged, proven) ----------------
__device__ __forceinline__ void load_stage(
    uint32_t stage_base,
    const __nv_bfloat16* __restrict__ Ah, const __nv_bfloat16* __restrict__ Al,
    const __nv_bfloat16* __restrict__ Bh, const __nv_bfloat16* __restrict__ Bl,
    int m0, int n0, int kc, int tid)
{
    const __nv_bfloat16* srcs[4] = {Ah, Al, Bh, Bl};
#pragma unroll
    for (int t = 0; t < 4; t++) {
        const __nv_bfloat16* base = srcs[t] + (size_t)(t < 2 ? m0 : n0) * DD + kc * KSTEP;
        uint32_t dst_tile = stage_base + t * TILE_BYTES;
#pragma unroll
        for (int i = 0; i < 2; i++) {
            int idx = tid + i * 256;
            int row = idx >> 2, c = idx & 3;
            CP_ASYNC16(dst_tile + row * ROWB + c * 16,
                       (const char*)(base + (size_t)row * DD) + c * 16);
        }
    }
}

__global__ __launch_bounds__(256) void gemm_ts(
    const __nv_bfloat16* __restrict__ Ah, const __nv_bfloat16* __restrict__ Al,
    const __nv_bfloat16* __restrict__ Bh, const __nv_bfloat16* __restrict__ Bl,
    float* __restrict__ C, int Ntot)
{
    extern __shared__ char smem[];
    uint32_t sb = smem_u32(smem);
    int tid = threadIdx.x;
    int wid = tid >> 5, lane = tid & 31;
    int wm = (wid & 3) * 32;
    int wn = (wid >> 2) * 64;
    int m0 = blockIdx.y * TM, n0 = blockIdx.x * TN;

    uint32_t aoff = (uint32_t)(wm + (lane & 15)) * ROWB + (lane >> 4) * 16;
    uint32_t boff = (uint32_t)(wn + (lane & 7) + ((lane >> 4) << 3)) * ROWB
                  + ((lane >> 3) & 1) * 16;

    float acc[2][8][4];
#pragma unroll
    for (int i = 0; i < 2; i++)
#pragma unroll
        for (int j = 0; j < 8; j++)
#pragma unroll
            for (int k = 0; k < 4; k++) acc[i][j][k] = 0.0f;

    load_stage(sb, Ah, Al, Bh, Bl, m0, n0, 0, tid);
    CP_COMMIT();
    load_stage(sb + STAGE_BYTES, Ah, Al, Bh, Bl, m0, n0, 1, tid);
    CP_COMMIT();

    for (int c = 0; c < NK; c++) {
        uint32_t st = sb + (c & 1) * STAGE_BYTES;
        if (c + 2 < NK) { CP_WAIT(1); } else { CP_WAIT(0); }
        __syncthreads();

        uint32_t baseAh = st + aoff;
        uint32_t baseAl = baseAh + TILE_BYTES;
        uint32_t baseBh = st + 2 * TILE_BYTES + boff;
        uint32_t baseBl = baseBh + TILE_BYTES;

#pragma unroll
        for (int kk = 0; kk < 2; kk++) {
            uint32_t koff = kk * 32;
            uint32_t ah[2][4], al[2][4], bh[4][4], bl[4][4];
#pragma unroll
            for (int mt = 0; mt < 2; mt++) {
                ldsm4(ah[mt], baseAh + mt * 16 * ROWB + koff);
                ldsm4(al[mt], baseAl + mt * 16 * ROWB + koff);
            }
#pragma unroll
            for (int np = 0; np < 4; np++) {
                ldsm4(bh[np], baseBh + np * 16 * ROWB + koff);
                ldsm4(bl[np], baseBl + np * 16 * ROWB + koff);
            }
#pragma unroll
            for (int mt = 0; mt < 2; mt++)
#pragma unroll
                for (int np = 0; np < 4; np++) {
                    mma16816(acc[mt][np*2],   ah[mt], &bh[np][0]);
                    mma16816(acc[mt][np*2],   ah[mt], &bl[np][0]);
                    mma16816(acc[mt][np*2],   al[mt], &bh[np][0]);
                    mma16816(acc[mt][np*2+1], ah[mt], &bh[np][2]);
                    mma16816(acc[mt][np*2+1], ah[mt], &bl[np][2]);
                    mma16816(acc[mt][np*2+1], al[mt], &bh[np][2]);
                }
        }
        __syncthreads();
        if (c + 2 < NK) {
            load_stage(st, Ah, Al, Bh, Bl, m0, n0, c + 2, tid);
            CP_COMMIT();
        }
    }

    int rbase = m0 + wm + (lane >> 2);
    int cbase = n0 + wn + 2 * (lane & 3);
#pragma unroll
    for (int mt = 0; mt < 2; mt++)
#pragma unroll
        for (int nt = 0; nt < 8; nt++) {
            float* p0 = C + (size_t)(rbase + mt * 16) * Ntot + cbase + nt * 8;
            float* p1 = C + (size_t)(rbase + mt * 16 + 8) * Ntot + cbase + nt * 8;
            *(float2*)p0 = make_float2(acc[mt][nt][0], acc[mt][nt][1]);
            *(float2*)p1 = make_float2(acc[mt][nt][2], acc[mt][nt][3]);
        }
}

// ---------------- flash attention on mma.sync (split bf16) ----------------
__device__ __forceinline__ void flash_load_kv(
    uint32_t st, const __nv_bfloat16* __restrict__ Kh, const __nv_bfloat16* __restrict__ Kl,
    const __nv_bfloat16* __restrict__ Vth, const __nv_bfloat16* __restrict__ Vtl,
    int bh, int k0, int tid)
{
#pragma unroll
    for (int i = 0; i < 2; i++) {
        int idx = tid + i * 256;            // 0..511
        int row = idx >> 3, c = idx & 7;    // 64 rows x 8 x 16B
        size_t krow = ((size_t)bh * TT + k0 + row) * DHD;
        CP_ASYNC16(st + row * FROWB + c * 16,             (const char*)(Kh + krow) + c * 16);
        CP_ASYNC16(st + FTILE + row * FROWB + c * 16,     (const char*)(Kl + krow) + c * 16);
        size_t vrow = ((size_t)bh * DHD + row) * TT + k0;
        CP_ASYNC16(st + 2 * FTILE + row * FROWB + c * 16, (const char*)(Vth + vrow) + c * 16);
        CP_ASYNC16(st + 3 * FTILE + row * FROWB + c * 16, (const char*)(Vtl + vrow) + c * 16);
    }
}

__global__ __launch_bounds__(256) void flash_mma(
    const __nv_bfloat16* __restrict__ Qh, const __nv_bfloat16* __restrict__ Ql,
    const __nv_bfloat16* __restrict__ Kh, const __nv_bfloat16* __restrict__ Kl,
    const __nv_bfloat16* __restrict__ Vth, const __nv_bfloat16* __restrict__ Vtl,
    __nv_bfloat16* __restrict__ AOh, __nv_bfloat16* __restrict__ AOl)
{
    extern __shared__ char smem[];
    uint32_t sb = smem_u32(smem);
    int tid = threadIdx.x, wid = tid >> 5, lane = tid & 31;
    int qblk = (TT / 128 - 1) - blockIdx.x;   // longest blocks first
    int bh = blockIdx.y;
    int q0 = qblk * 128;
    int wm = wid * 16;
    int nkt = 2 * qblk + 2;

    // ---- load Q (128 rows x 64, hi+lo) into stage0 area, consume to regs
#pragma unroll
    for (int i = 0; i < 4; i++) {
        int idx = tid + i * 256;            // 0..1023
        int row = idx >> 3, c = idx & 7;
        size_t qrow = ((size_t)bh * TT + q0 + row) * DHD;
        CP_ASYNC16(sb + row * FROWB + c * 16,              (const char*)(Qh + qrow) + c * 16);
        CP_ASYNC16(sb + 128 * FROWB + row * FROWB + c * 16,(const char*)(Ql + qrow) + c * 16);
    }
    CP_COMMIT(); CP_WAIT(0);
    __syncthreads();
    uint32_t qaddr = sb + (uint32_t)(wm + (lane & 15)) * FROWB + (lane >> 4) * 16;
    uint32_t qfh[4][4], qfl[4][4];
#pragma unroll
    for (int s = 0; s < 4; s++) {
        ldsm4(qfh[s], qaddr + s * 32);
        ldsm4(qfl[s], qaddr + 128 * FROWB + s * 32);
    }
    __syncthreads();    // stage0 free

    float o[8][4];
#pragma unroll
    for (int j = 0; j < 8; j++)
#pragma unroll
        for (int k = 0; k < 4; k++) o[j][k] = 0.0f;
    float mrow0 = -1e30f, mrow1 = -1e30f, lrow0 = 0.0f, lrow1 = 0.0f;

    flash_load_kv(sb, Kh, Kl, Vth, Vtl, bh, 0, tid);
    CP_COMMIT();
    flash_load_kv(sb + FSTAGE, Kh, Kl, Vth, Vtl, bh, 64, tid);
    CP_COMMIT();

    uint32_t bpat = (uint32_t)((lane & 7) + ((lane >> 4) << 3)) * FROWB + ((lane >> 3) & 1) * 16;

    for (int kt = 0; kt < nkt; kt++) {
        uint32_t st = sb + (kt & 1) * FSTAGE;
        if (kt + 2 < nkt) { CP_WAIT(1); } else { CP_WAIT(0); }
        __syncthreads();

        // ---- S = Q K^T (3-term split), fp32 frags
        float s[8][4];
#pragma unroll
        for (int j = 0; j < 8; j++)
#pragma unroll
            for (int k = 0; k < 4; k++) s[j][k] = 0.0f;
        uint32_t baseKh = st + bpat, baseKl = baseKh + FTILE;
#pragma unroll
        for (int ks = 0; ks < 4; ks++) {
            uint32_t koff = ks * 32;
            uint32_t kbh[4][4], kbl[4][4];
#pragma unroll
            for (int np = 0; np < 4; np++) {
                ldsm4(kbh[np], baseKh + np * 16 * FROWB + koff);
                ldsm4(kbl[np], baseKl + np * 16 * FROWB + koff);
            }
#pragma unroll
            for (int np = 0; np < 4; np++) {
                mma16816(s[np*2],   qfh[ks], &kbh[np][0]);
                mma16816(s[np*2],   qfh[ks], &kbl[np][0]);
                mma16816(s[np*2],   qfl[ks], &kbh[np][0]);
                mma16816(s[np*2+1], qfh[ks], &kbh[np][2]);
                mma16816(s[np*2+1], qfh[ks], &kbl[np][2]);
                mma16816(s[np*2+1], qfl[ks], &kbh[np][2]);
            }
        }

        // ---- causal mask (only tiles touching the diagonal for this warp)
        int row0 = q0 + wm + (lane >> 2);
        if (kt * 64 + 63 > row0) {
#pragma unroll
            for (int j = 0; j < 8; j++) {
                int colb = kt * 64 + j * 8 + 2 * (lane & 3);
                if (colb     > row0)     s[j][0] = -1e30f;
                if (colb + 1 > row0)     s[j][1] = -1e30f;
                if (colb     > row0 + 8) s[j][2] = -1e30f;
                if (colb + 1 > row0 + 8) s[j][3] = -1e30f;
            }
        }

        // ---- online softmax (rows r and r+8)
        float mx0 = -1e30f, mx1 = -1e30f;
#pragma unroll
        for (int j = 0; j < 8; j++) {
            mx0 = fmaxf(mx0, fmaxf(s[j][0], s[j][1]));
            mx1 = fmaxf(mx1, fmaxf(s[j][2], s[j][3]));
        }
        mx0 = fmaxf(mx0, __shfl_xor_sync(0xffffffff, mx0, 1));
        mx0 = fmaxf(mx0, __shfl_xor_sync(0xffffffff, mx0, 2));
        mx1 = fmaxf(mx1, __shfl_xor_sync(0xffffffff, mx1, 1));
        mx1 = fmaxf(mx1, __shfl_xor_sync(0xffffffff, mx1, 2));
        float mn0 = fmaxf(mrow0, mx0), mn1 = fmaxf(mrow1, mx1);
        float cr0 = __expf(mrow0 - mn0), cr1 = __expf(mrow1 - mn1);
        lrow0 *= cr0; lrow1 *= cr1;
#pragma unroll
        for (int j = 0; j < 8; j++) {
            o[j][0] *= cr0; o[j][1] *= cr0;
            o[j][2] *= cr1; o[j][3] *= cr1;
        }
        mrow0 = mn0; mrow1 = mn1;

        float ls0 = 0.0f, ls1 = 0.0f;
        uint32_t ph[8][2], pl[8][2];
#pragma unroll
        for (int j = 0; j < 8; j++) {
            float p0 = __expf(s[j][0] - mn0), p1 = __expf(s[j][1] - mn0);
            float p2 = __expf(s[j][2] - mn1), p3 = __expf(s[j][3] - mn1);
            ls0 += p0 + p1; ls1 += p2 + p3;
            __nv_bfloat162 h0 = __floats2bfloat162_rn(p0, p1);
            __nv_bfloat162 h1 = __floats2bfloat162_rn(p2, p3);
            ph[j][0] = *(uint32_t*)&h0; ph[j][1] = *(uint32_t*)&h1;
            __nv_bfloat162 l0 = __floats2bfloat162_rn(p0 - __low2float(h0), p1 - __high2float(h0));
            __nv_bfloat162 l1 = __floats2bfloat162_rn(p2 - __low2float(h1), p3 - __high2float(h1));
            pl[j][0] = *(uint32_t*)&l0; pl[j][1] = *(uint32_t*)&l1;
        }
        ls0 += __shfl_xor_sync(0xffffffff, ls0, 1);
        ls0 += __shfl_xor_sync(0xffffffff, ls0, 2);
        ls1 += __shfl_xor_sync(0xffffffff, ls1, 1);
        ls1 += __shfl_xor_sync(0xffffffff, ls1, 2);
        lrow0 += ls0; lrow1 += ls1;

        // ---- O += P V (3-term split); S-frags ARE the A-frags of P
        uint32_t baseVh = st + 2 * FTILE + bpat, baseVl = baseVh + FTILE;
#pragma unroll
        for (int ks = 0; ks < 4; ks++) {
            uint32_t ath[4] = { ph[2*ks][0], ph[2*ks][1], ph[2*ks+1][0], ph[2*ks+1][1] };
            uint32_t atl[4] = { pl[2*ks][0], pl[2*ks][1], pl[2*ks+1][0], pl[2*ks+1][1] };
            uint32_t koff = ks * 32;
            uint32_t vbh[4][4], vbl[4][4];
#pragma unroll
            for (int np = 0; np < 4; np++) {
                ldsm4(vbh[np], baseVh + np * 16 * FROWB + koff);
                ldsm4(vbl[np], baseVl + np * 16 * FROWB + koff);
            }
#pragma unroll
            for (int np = 0; np < 4; np++) {
                mma16816(o[np*2],   ath, &vbh[np][0]);
                mma16816(o[np*2],   ath, &vbl[np][0]);
                mma16816(o[np*2],   atl, &vbh[np][0]);
                mma16816(o[np*2+1], ath, &vbh[np][2]);
                mma16816(o[np*2+1], ath, &vbl[np][2]);
                mma16816(o[np*2+1], atl, &vbh[np][2]);
            }
        }
        __syncthreads();
        if (kt + 2 < nkt) {
            flash_load_kv(st, Kh, Kl, Vth, Vtl, bh, (kt + 2) * 64, tid);
            CP_COMMIT();
        }
    }

    // ---- epilogue: normalize, split to bf16 hi/lo, write AO [b][t][1024]
    float inv0 = 1.0f / lrow0, inv1 = 1.0f / lrow1;
    int b = bh >> 4, h = bh & 15;
    int r0 = q0 + wm + (lane >> 2);
    size_t base0 = (size_t)(b * TT + r0) * DD + h * DHD + 2 * (lane & 3);
    size_t base1 = base0 + (size_t)8 * DD;
#pragma unroll
    for (int j = 0; j < 8; j++) {
        float f0 = o[j][0] * inv0, f1 = o[j][1] * inv0;
        float f2 = o[j][2] * inv1, f3 = o[j][3] * inv1;
        __nv_bfloat162 h0 = __floats2bfloat162_rn(f0, f1);
        __nv_bfloat162 h1 = __floats2bfloat162_rn(f2, f3);
        __nv_bfloat162 l0 = __floats2bfloat162_rn(f0 - __low2float(h0), f1 - __high2float(h0));
        __nv_bfloat162 l1 = __floats2bfloat162_rn(f2 - __low2float(h1), f3 - __high2float(h1));
        *(__nv_bfloat162*)(AOh + base0 + j * 8) = h0;
        *(__nv_bfloat162*)(AOl + base0 + j * 8) = l0;
        *(__nv_bfloat162*)(AOh + base1 + j * 8) = h1;
        *(__nv_bfloat162*)(AOl + base1 + j * 8) = l1;
    }
}

// ---------------- launch ----------------
extern "C" void kernel_launch(void* const* d_in, const int* in_sizes, int n_in,
                              void* d_out, int out_size) {
    const float* x    = (const float*)d_in[0];
    const float* wq_w = (const float*)d_in[2];
    const float* wq_A = (const float*)d_in[3];
    const float* wq_B = (const float*)d_in[4];
    const float* wk_w = (const float*)d_in[5];
    const float* wv_w = (const float*)d_in[6];
    const float* wv_A = (const float*)d_in[7];
    const float* wv_B = (const float*)d_in[8];
    const float* wo_w = (const float*)d_in[9];
    float* out = (float*)d_out;

    static bool attr_set = false;
    if (!attr_set) {
        cudaFuncSetAttribute(gemm_ts,  cudaFuncAttributeMaxDynamicSharedMemorySize, SMEM_TOTAL);
        cudaFuncSetAttribute(flash_mma, cudaFuncAttributeMaxDynamicSharedMemorySize, FSMEM);
        attr_set = true;
    }

    __nv_bfloat16 *Xh, *Xl, *Wh, *Wl, *WOh, *WOl;
    __nv_bfloat16 *Qh, *Ql, *Kh, *Kl, *Vth, *Vtl, *AOh, *AOl;
    float *QKV;
    cudaGetSymbolAddress((void**)&Xh,  g_Xh);
    cudaGetSymbolAddress((void**)&Xl,  g_Xl);
    cudaGetSymbolAddress((void**)&Wh,  g_Wh);
    cudaGetSymbolAddress((void**)&Wl,  g_Wl);
    cudaGetSymbolAddress((void**)&WOh, g_WOh);
    cudaGetSymbolAddress((void**)&WOl, g_WOl);
    cudaGetSymbolAddress((void**)&Qh,  g_Qh);
    cudaGetSymbolAddress((void**)&Ql,  g_Ql);
    cudaGetSymbolAddress((void**)&Kh,  g_Kh);
    cudaGetSymbolAddress((void**)&Kl,  g_Kl);
    cudaGetSymbolAddress((void**)&Vth, g_Vth);
    cudaGetSymbolAddress((void**)&Vtl, g_Vtl);
    cudaGetSymbolAddress((void**)&AOh, g_AOh);
    cudaGetSymbolAddress((void**)&AOl, g_AOl);
    cudaGetSymbolAddress((void**)&QKV, g_QKV);

    split_kernel<<<(MTOT * DD) / 256, 256>>>(x, Xh, Xl, MTOT * DD);
    prep_wcat<<<(NQKV * DD) / 256, 256>>>(wq_w, wq_A, wq_B, wk_w, wv_w, wv_A, wv_B, Wh, Wl);
    split_kernel<<<(DD * DD) / 256, 256>>>(wo_w, WOh, WOl, DD * DD);

    gemm_ts<<<dim3(NQKV / TN, MTOT / TM), 256, SMEM_TOTAL>>>(Xh, Xl, Wh, Wl, QKV, NQKV);

    convert_qkv<<<dim3(TT / 64, BB * HH), 256>>>(QKV, Qh, Ql, Kh, Kl, Vth, Vtl);

    flash_mma<<<dim3(TT / 128, BB * HH), 256, FSMEM>>>(Qh, Ql, Kh, Kl, Vth, Vtl, AOh, AOl);

    gemm_ts<<<dim3(DD / TN, MTOT / TM), 256, SMEM_TOTAL>>>(AOh, AOl, WOh, WOl, out, DD);
}

// round 5
// speedup vs baseline: 3.3178x; 1.0255x over previous
#include <cuda_runtime.h>
#include <cuda_bf16.h>
#include <cstdint>

#define DD    1024
#define TT    2048
#define BB    2
#define MTOT  4096
#define HH    16
#define DHD   64
#define RR    8
#define NQKV  3072

// ---- mma.sync GEMM tiling ----
#define TM 128
#define TN 128
#define KSTEP 32
#define NK (DD / KSTEP)             // 32
#define ROWB 80
#define TILE_BYTES (128 * ROWB)
#define STAGE_BYTES (4 * TILE_BYTES)
#define SMEM_TOTAL (2 * STAGE_BYTES)

// ---- flash tiling ----
#define FROWB 144                   // 128B data + 16B pad
#define FTILE (64 * FROWB)          // 9216
#define FSTAGE (4 * FTILE)          // 36864  (Kh,Kl,Vh,Vl)
#define FSMEM (2 * FSTAGE)          // 73728

// ---- scratch ----
__device__ __nv_bfloat16 g_Xh [MTOT * DD];
__device__ __nv_bfloat16 g_Xl [MTOT * DD];
__device__ __nv_bfloat16 g_Wh [NQKV * DD];
__device__ __nv_bfloat16 g_Wl [NQKV * DD];
__device__ __nv_bfloat16 g_WOh[DD * DD];
__device__ __nv_bfloat16 g_WOl[DD * DD];
__device__ __nv_bfloat16 g_Qh [MTOT * DD];
__device__ __nv_bfloat16 g_Ql [MTOT * DD];
__device__ __nv_bfloat16 g_Kh [MTOT * DD];
__device__ __nv_bfloat16 g_Kl [MTOT * DD];
__device__ __nv_bfloat16 g_Vh [MTOT * DD];
__device__ __nv_bfloat16 g_Vl [MTOT * DD];
__device__ __nv_bfloat16 g_AOh[MTOT * DD];
__device__ __nv_bfloat16 g_AOl[MTOT * DD];

// ---------------- PTX helpers ----------------
__device__ __forceinline__ uint32_t smem_u32(const void* p) {
    uint32_t a;
    asm("{ .reg .u64 t; cvta.to.shared.u64 t, %1; cvt.u32.u64 %0, t; }" : "=r"(a) : "l"(p));
    return a;
}
#define CP_ASYNC16(dst, src) \
    asm volatile("cp.async.cg.shared.global [%0], [%1], 16;" :: "r"(dst), "l"(src))
#define CP_COMMIT()   asm volatile("cp.async.commit_group;" ::: "memory")
#define CP_WAIT(n)    asm volatile("cp.async.wait_group %0;" :: "n"(n) : "memory")

__device__ __forceinline__ void ldsm4(uint32_t* r, uint32_t addr) {
    asm volatile("ldmatrix.sync.aligned.m8n8.x4.shared.b16 {%0,%1,%2,%3}, [%4];"
                 : "=r"(r[0]), "=r"(r[1]), "=r"(r[2]), "=r"(r[3]) : "r"(addr));
}
__device__ __forceinline__ void ldsm4t(uint32_t* r, uint32_t addr) {
    asm volatile("ldmatrix.sync.aligned.m8n8.x4.trans.shared.b16 {%0,%1,%2,%3}, [%4];"
                 : "=r"(r[0]), "=r"(r[1]), "=r"(r[2]), "=r"(r[3]) : "r"(addr));
}
__device__ __forceinline__ void mma16816(float* c, const uint32_t* a, const uint32_t* b) {
    asm volatile("mma.sync.aligned.m16n8k16.row.col.f32.bf16.bf16.f32 "
                 "{%0,%1,%2,%3}, {%4,%5,%6,%7}, {%8,%9}, {%0,%1,%2,%3};"
                 : "+f"(c[0]), "+f"(c[1]), "+f"(c[2]), "+f"(c[3])
                 : "r"(a[0]), "r"(a[1]), "r"(a[2]), "r"(a[3]), "r"(b[0]), "r"(b[1]));
}

// ---------------- prep kernels ----------------
__global__ void split_kernel(const float* __restrict__ s, __nv_bfloat16* __restrict__ h,
                             __nv_bfloat16* __restrict__ l, int n) {
    int i = blockIdx.x * blockDim.x + threadIdx.x;
    if (i >= n) return;
    float v = s[i];
    __nv_bfloat16 hb = __float2bfloat16(v);
    h[i] = hb;
    l[i] = __float2bfloat16(v - __bfloat162float(hb));
}

__global__ void prep_wcat(const float* __restrict__ wq, const float* __restrict__ qA,
                          const float* __restrict__ qB, const float* __restrict__ wk,
                          const float* __restrict__ wv, const float* __restrict__ vA,
                          const float* __restrict__ vB,
                          __nv_bfloat16* __restrict__ Wh, __nv_bfloat16* __restrict__ Wl) {
    int i = blockIdx.x * blockDim.x + threadIdx.x;
    if (i >= NQKV * DD) return;
    int o = i / DD, c = i % DD;
    float v;
    if (o < 1024) {
        v = wq[o * DD + c];
#pragma unroll
        for (int r = 0; r < RR; r++) v += 2.0f * qB[o * RR + r] * qA[r * DD + c];
    } else if (o < 2048) {
        v = wk[(o - 1024) * DD + c];
    } else {
        int oo = o - 2048;
        v = wv[oo * DD + c];
#pragma unroll
        for (int r = 0; r < RR; r++) v += 2.0f * vB[oo * RR + r] * vA[r * DD + c];
    }
    __nv_bfloat16 hb = __float2bfloat16(v);
    Wh[i] = hb;
    Wl[i] = __float2bfloat16(v - __bfloat162float(hb));
}

// ---------------- mma.sync split-bf16 GEMM ----------------
__device__ __forceinline__ void load_stage(
    uint32_t stage_base,
    const __nv_bfloat16* __restrict__ Ah, const __nv_bfloat16* __restrict__ Al,
    const __nv_bfloat16* __restrict__ Bh, const __nv_bfloat16* __restrict__ Bl,
    int m0, int n0, int kc, int tid)
{
    const __nv_bfloat16* srcs[4] = {Ah, Al, Bh, Bl};
#pragma unroll
    for (int t = 0; t < 4; t++) {
        const __nv_bfloat16* base = srcs[t] + (size_t)(t < 2 ? m0 : n0) * DD + kc * KSTEP;
        uint32_t dst_tile = stage_base + t * TILE_BYTES;
#pragma unroll
        for (int i = 0; i < 2; i++) {
            int idx = tid + i * 256;
            int row = idx >> 2, c = idx & 3;
            CP_ASYNC16(dst_tile + row * ROWB + c * 16,
                       (const char*)(base + (size_t)row * DD) + c * 16);
        }
    }
}

// MODE 0: write fp32 C.  MODE 1: fused QKV epilogue (split bf16 per-head, Q scaled)
template<int MODE>
__global__ __launch_bounds__(256) void gemm_ts(
    const __nv_bfloat16* __restrict__ Ah, const __nv_bfloat16* __restrict__ Al,
    const __nv_bfloat16* __restrict__ Bh, const __nv_bfloat16* __restrict__ Bl,
    float* __restrict__ C, int Ntot,
    __nv_bfloat16* __restrict__ Qh, __nv_bfloat16* __restrict__ Ql,
    __nv_bfloat16* __restrict__ Kh, __nv_bfloat16* __restrict__ Kl,
    __nv_bfloat16* __restrict__ Vh, __nv_bfloat16* __restrict__ Vl)
{
    extern __shared__ char smem[];
    uint32_t sb = smem_u32(smem);
    int tid = threadIdx.x;
    int wid = tid >> 5, lane = tid & 31;
    int wm = (wid & 3) * 32;
    int wn = (wid >> 2) * 64;
    int m0 = blockIdx.y * TM, n0 = blockIdx.x * TN;

    uint32_t aoff = (uint32_t)(wm + (lane & 15)) * ROWB + (lane >> 4) * 16;
    uint32_t boff = (uint32_t)(wn + (lane & 7) + ((lane >> 4) << 3)) * ROWB
                  + ((lane >> 3) & 1) * 16;

    float acc[2][8][4];
#pragma unroll
    for (int i = 0; i < 2; i++)
#pragma unroll
        for (int j = 0; j < 8; j++)
#pragma unroll
            for (int k = 0; k < 4; k++) acc[i][j][k] = 0.0f;

    load_stage(sb, Ah, Al, Bh, Bl, m0, n0, 0, tid);
    CP_COMMIT();
    load_stage(sb + STAGE_BYTES, Ah, Al, Bh, Bl, m0, n0, 1, tid);
    CP_COMMIT();

    for (int c = 0; c < NK; c++) {
        uint32_t st = sb + (c & 1) * STAGE_BYTES;
        if (c + 2 < NK) { CP_WAIT(1); } else { CP_WAIT(0); }
        __syncthreads();

        uint32_t baseAh = st + aoff;
        uint32_t baseAl = baseAh + TILE_BYTES;
        uint32_t baseBh = st + 2 * TILE_BYTES + boff;
        uint32_t baseBl = baseBh + TILE_BYTES;

#pragma unroll
        for (int kk = 0; kk < 2; kk++) {
            uint32_t koff = kk * 32;
            uint32_t ah[2][4], al[2][4], bh[4][4], bl[4][4];
#pragma unroll
            for (int mt = 0; mt < 2; mt++) {
                ldsm4(ah[mt], baseAh + mt * 16 * ROWB + koff);
                ldsm4(al[mt], baseAl + mt * 16 * ROWB + koff);
            }
#pragma unroll
            for (int np = 0; np < 4; np++) {
                ldsm4(bh[np], baseBh + np * 16 * ROWB + koff);
                ldsm4(bl[np], baseBl + np * 16 * ROWB + koff);
            }
            // term-major issue: 16 independent MMAs per term
#pragma unroll
            for (int mt = 0; mt < 2; mt++)
#pragma unroll
                for (int np = 0; np < 4; np++) {
                    mma16816(acc[mt][np*2],   ah[mt], &bh[np][0]);
                    mma16816(acc[mt][np*2+1], ah[mt], &bh[np][2]);
                }
#pragma unroll
            for (int mt = 0; mt < 2; mt++)
#pragma unroll
                for (int np = 0; np < 4; np++) {
                    mma16816(acc[mt][np*2],   ah[mt], &bl[np][0]);
                    mma16816(acc[mt][np*2+1], ah[mt], &bl[np][2]);
                }
#pragma unroll
            for (int mt = 0; mt < 2; mt++)
#pragma unroll
                for (int np = 0; np < 4; np++) {
                    mma16816(acc[mt][np*2],   al[mt], &bh[np][0]);
                    mma16816(acc[mt][np*2+1], al[mt], &bh[np][2]);
                }
        }
        __syncthreads();
        if (c + 2 < NK) {
            load_stage(st, Ah, Al, Bh, Bl, m0, n0, c + 2, tid);
            CP_COMMIT();
        }
    }

    if (MODE == 0) {
        int rbase = m0 + wm + (lane >> 2);
        int cbase = n0 + wn + 2 * (lane & 3);
#pragma unroll
        for (int mt = 0; mt < 2; mt++)
#pragma unroll
            for (int nt = 0; nt < 8; nt++) {
                float* p0 = C + (size_t)(rbase + mt * 16) * Ntot + cbase + nt * 8;
                float* p1 = C + (size_t)(rbase + mt * 16 + 8) * Ntot + cbase + nt * 8;
                *(float2*)p0 = make_float2(acc[mt][nt][0], acc[mt][nt][1]);
                *(float2*)p1 = make_float2(acc[mt][nt][2], acc[mt][nt][3]);
            }
    } else {
        // fused QKV epilogue: n in [0,3072) -> sector (Q/K/V), head, d
        int colbase = n0 + wn;                  // 64-aligned -> single head per warp
        int sector = colbase >> 10;
        int h = (colbase & 1023) >> 6;
        int d0 = 2 * (lane & 3);
        float scale = (sector == 0) ? 0.125f : 1.0f;
        __nv_bfloat16* Dh = (sector == 0) ? Qh : (sector == 1) ? Kh : Vh;
        __nv_bfloat16* Dl = (sector == 0) ? Ql : (sector == 1) ? Kl : Vl;
#pragma unroll
        for (int mt = 0; mt < 2; mt++) {
            int mrow0 = m0 + wm + (lane >> 2) + mt * 16;
            int mrow1 = mrow0 + 8;
            size_t base0 = ((size_t)((mrow0 >> 11) * HH + h) * TT + (mrow0 & 2047)) * DHD + d0;
            size_t base1 = ((size_t)((mrow1 >> 11) * HH + h) * TT + (mrow1 & 2047)) * DHD + d0;
#pragma unroll
            for (int nt = 0; nt < 8; nt++) {
                float f0 = acc[mt][nt][0] * scale, f1 = acc[mt][nt][1] * scale;
                float f2 = acc[mt][nt][2] * scale, f3 = acc[mt][nt][3] * scale;
                __nv_bfloat162 h0 = __floats2bfloat162_rn(f0, f1);
                __nv_bfloat162 h1 = __floats2bfloat162_rn(f2, f3);
                __nv_bfloat162 l0 = __floats2bfloat162_rn(f0 - __low2float(h0), f1 - __high2float(h0));
                __nv_bfloat162 l1 = __floats2bfloat162_rn(f2 - __low2float(h1), f3 - __high2float(h1));
                *(__nv_bfloat162*)(Dh + base0 + nt * 8) = h0;
                *(__nv_bfloat162*)(Dl + base0 + nt * 8) = l0;
                *(__nv_bfloat162*)(Dh + base1 + nt * 8) = h1;
                *(__nv_bfloat162*)(Dl + base1 + nt * 8) = l1;
            }
        }
    }
}

// ---------------- flash attention on mma.sync (split bf16) ----------------
__device__ __forceinline__ void flash_load_kv(
    uint32_t st, const __nv_bfloat16* __restrict__ Kh, const __nv_bfloat16* __restrict__ Kl,
    const __nv_bfloat16* __restrict__ Vh, const __nv_bfloat16* __restrict__ Vl,
    int bh, int k0, int tid)
{
#pragma unroll
    for (int i = 0; i < 2; i++) {
        int idx = tid + i * 256;            // 0..511
        int row = idx >> 3, c = idx & 7;    // 64 rows x 8 x 16B
        size_t krow = ((size_t)bh * TT + k0 + row) * DHD;
        CP_ASYNC16(st + row * FROWB + c * 16,             (const char*)(Kh + krow) + c * 16);
        CP_ASYNC16(st + FTILE + row * FROWB + c * 16,     (const char*)(Kl + krow) + c * 16);
        CP_ASYNC16(st + 2 * FTILE + row * FROWB + c * 16, (const char*)(Vh + krow) + c * 16);
        CP_ASYNC16(st + 3 * FTILE + row * FROWB + c * 16, (const char*)(Vl + krow) + c * 16);
    }
}

__global__ __launch_bounds__(256) void flash_mma(
    const __nv_bfloat16* __restrict__ Qh, const __nv_bfloat16* __restrict__ Ql,
    const __nv_bfloat16* __restrict__ Kh, const __nv_bfloat16* __restrict__ Kl,
    const __nv_bfloat16* __restrict__ Vh, const __nv_bfloat16* __restrict__ Vl,
    __nv_bfloat16* __restrict__ AOh, __nv_bfloat16* __restrict__ AOl)
{
    extern __shared__ char smem[];
    uint32_t sb = smem_u32(smem);
    int tid = threadIdx.x, wid = tid >> 5, lane = tid & 31;
    int qblk = (TT / 128 - 1) - blockIdx.x;   // longest blocks first
    int bh = blockIdx.y;
    int q0 = qblk * 128;
    int wm = wid * 16;
    int nkt = 2 * qblk + 2;

    // ---- load Q (128 rows x 64, hi+lo) into stage0 area, consume to regs
#pragma unroll
    for (int i = 0; i < 4; i++) {
        int idx = tid + i * 256;
        int row = idx >> 3, c = idx & 7;
        size_t qrow = ((size_t)bh * TT + q0 + row) * DHD;
        CP_ASYNC16(sb + row * FROWB + c * 16,               (const char*)(Qh + qrow) + c * 16);
        CP_ASYNC16(sb + 128 * FROWB + row * FROWB + c * 16, (const char*)(Ql + qrow) + c * 16);
    }
    CP_COMMIT(); CP_WAIT(0);
    __syncthreads();
    uint32_t qaddr = sb + (uint32_t)(wm + (lane & 15)) * FROWB + (lane >> 4) * 16;
    uint32_t qfh[4][4], qfl[4][4];
#pragma unroll
    for (int s = 0; s < 4; s++) {
        ldsm4(qfh[s], qaddr + s * 32);
        ldsm4(qfl[s], qaddr + 128 * FROWB + s * 32);
    }
    __syncthreads();

    float o[8][4];
#pragma unroll
    for (int j = 0; j < 8; j++)
#pragma unroll
        for (int k = 0; k < 4; k++) o[j][k] = 0.0f;
    float mrow0 = -1e30f, mrow1 = -1e30f, lrow0 = 0.0f, lrow1 = 0.0f;

    flash_load_kv(sb, Kh, Kl, Vh, Vl, bh, 0, tid);
    CP_COMMIT();
    flash_load_kv(sb + FSTAGE, Kh, Kl, Vh, Vl, bh, 64, tid);
    CP_COMMIT();

    uint32_t bpat = (uint32_t)((lane & 7) + ((lane >> 4) << 3)) * FROWB + ((lane >> 3) & 1) * 16;
    // trans pattern for V (B operand of PV): row t = lane&15, col byte = (lane>>4)*16
    uint32_t vpat = (uint32_t)(lane & 15) * FROWB + ((lane >> 4) << 4);

    for (int kt = 0; kt < nkt; kt++) {
        uint32_t st = sb + (kt & 1) * FSTAGE;
        if (kt + 2 < nkt) { CP_WAIT(1); } else { CP_WAIT(0); }
        __syncthreads();

        // ---- S = Q K^T (3-term split)
        float s[8][4];
#pragma unroll
        for (int j = 0; j < 8; j++)
#pragma unroll
            for (int k = 0; k < 4; k++) s[j][k] = 0.0f;
        uint32_t baseKh = st + bpat, baseKl = baseKh + FTILE;
#pragma unroll
        for (int ks = 0; ks < 4; ks++) {
            uint32_t koff = ks * 32;
            uint32_t kbh[4][4], kbl[4][4];
#pragma unroll
            for (int np = 0; np < 4; np++) {
                ldsm4(kbh[np], baseKh + np * 16 * FROWB + koff);
                ldsm4(kbl[np], baseKl + np * 16 * FROWB + koff);
            }
#pragma unroll
            for (int np = 0; np < 4; np++) {
                mma16816(s[np*2],   qfh[ks], &kbh[np][0]);
                mma16816(s[np*2+1], qfh[ks], &kbh[np][2]);
            }
#pragma unroll
            for (int np = 0; np < 4; np++) {
                mma16816(s[np*2],   qfh[ks], &kbl[np][0]);
                mma16816(s[np*2+1], qfh[ks], &kbl[np][2]);
            }
#pragma unroll
            for (int np = 0; np < 4; np++) {
                mma16816(s[np*2],   qfl[ks], &kbh[np][0]);
                mma16816(s[np*2+1], qfl[ks], &kbh[np][2]);
            }
        }

        // ---- causal mask
        int row0 = q0 + wm + (lane >> 2);
        if (kt * 64 + 63 > row0) {
#pragma unroll
            for (int j = 0; j < 8; j++) {
                int colb = kt * 64 + j * 8 + 2 * (lane & 3);
                if (colb     > row0)     s[j][0] = -1e30f;
                if (colb + 1 > row0)     s[j][1] = -1e30f;
                if (colb     > row0 + 8) s[j][2] = -1e30f;
                if (colb + 1 > row0 + 8) s[j][3] = -1e30f;
            }
        }

        // ---- online softmax
        float mx0 = -1e30f, mx1 = -1e30f;
#pragma unroll
        for (int j = 0; j < 8; j++) {
            mx0 = fmaxf(mx0, fmaxf(s[j][0], s[j][1]));
            mx1 = fmaxf(mx1, fmaxf(s[j][2], s[j][3]));
        }
        mx0 = fmaxf(mx0, __shfl_xor_sync(0xffffffff, mx0, 1));
        mx0 = fmaxf(mx0, __shfl_xor_sync(0xffffffff, mx0, 2));
        mx1 = fmaxf(mx1, __shfl_xor_sync(0xffffffff, mx1, 1));
        mx1 = fmaxf(mx1, __shfl_xor_sync(0xffffffff, mx1, 2));
        float mn0 = fmaxf(mrow0, mx0), mn1 = fmaxf(mrow1, mx1);
        float cr0 = __expf(mrow0 - mn0), cr1 = __expf(mrow1 - mn1);
        lrow0 *= cr0; lrow1 *= cr1;
#pragma unroll
        for (int j = 0; j < 8; j++) {
            o[j][0] *= cr0; o[j][1] *= cr0;
            o[j][2] *= cr1; o[j][3] *= cr1;
        }
        mrow0 = mn0; mrow1 = mn1;

        float ls0 = 0.0f, ls1 = 0.0f;
        uint32_t ph[8][2], pl[8][2];
#pragma unroll
        for (int j = 0; j < 8; j++) {
            float p0 = __expf(s[j][0] - mn0), p1 = __expf(s[j][1] - mn0);
            float p2 = __expf(s[j][2] - mn1), p3 = __expf(s[j][3] - mn1);
            ls0 += p0 + p1; ls1 += p2 + p3;
            __nv_bfloat162 h0 = __floats2bfloat162_rn(p0, p1);
            __nv_bfloat162 h1 = __floats2bfloat162_rn(p2, p3);
            ph[j][0] = *(uint32_t*)&h0; ph[j][1] = *(uint32_t*)&h1;
            __nv_bfloat162 l0 = __floats2bfloat162_rn(p0 - __low2float(h0), p1 - __high2float(h0));
            __nv_bfloat162 l1 = __floats2bfloat162_rn(p2 - __low2float(h1), p3 - __high2float(h1));
            pl[j][0] = *(uint32_t*)&l0; pl[j][1] = *(uint32_t*)&l1;
        }
        ls0 += __shfl_xor_sync(0xffffffff, ls0, 1);
        ls0 += __shfl_xor_sync(0xffffffff, ls0, 2);
        ls1 += __shfl_xor_sync(0xffffffff, ls1, 1);
        ls1 += __shfl_xor_sync(0xffffffff, ls1, 2);
        lrow0 += ls0; lrow1 += ls1;

        // ---- O += P V (V via ldmatrix.trans from [t][d] tiles)
        uint32_t baseVh = st + 2 * FTILE + vpat, baseVl = baseVh + FTILE;
#pragma unroll
        for (int ks = 0; ks < 4; ks++) {
            uint32_t ath[4] = { ph[2*ks][0], ph[2*ks][1], ph[2*ks+1][0], ph[2*ks+1][1] };
            uint32_t atl[4] = { pl[2*ks][0], pl[2*ks][1], pl[2*ks+1][0], pl[2*ks+1][1] };
            uint32_t roff = ks * 16 * FROWB;      // k = t offset (rows)
            uint32_t vbh[4][4], vbl[4][4];
#pragma unroll
            for (int np = 0; np < 4; np++) {
                ldsm4t(vbh[np], baseVh + roff + np * 32);   // np*16 cols * 2B
                ldsm4t(vbl[np], baseVl + roff + np * 32);
            }
#pragma unroll
            for (int np = 0; np < 4; np++) {
                mma16816(o[np*2],   ath, &vbh[np][0]);
                mma16816(o[np*2+1], ath, &vbh[np][2]);
            }
#pragma unroll
            for (int np = 0; np < 4; np++) {
                mma16816(o[np*2],   ath, &vbl[np][0]);
                mma16816(o[np*2+1], ath, &vbl[np][2]);
            }
#pragma unroll
            for (int np = 0; np < 4; np++) {
                mma16816(o[np*2],   atl, &vbh[np][0]);
                mma16816(o[np*2+1], atl, &vbh[np][2]);
            }
        }
        __syncthreads();
        if (kt + 2 < nkt) {
            flash_load_kv(st, Kh, Kl, Vh, Vl, bh, (kt + 2) * 64, tid);
            CP_COMMIT();
        }
    }

    // ---- epilogue
    float inv0 = 1.0f / lrow0, inv1 = 1.0f / lrow1;
    int b = bh >> 4, h = bh & 15;
    int r0 = q0 + wm + (lane >> 2);
    size_t base0 = (size_t)(b * TT + r0) * DD + h * DHD + 2 * (lane & 3);
    size_t base1 = base0 + (size_t)8 * DD;
#pragma unroll
    for (int j = 0; j < 8; j++) {
        float f0 = o[j][0] * inv0, f1 = o[j][1] * inv0;
        float f2 = o[j][2] * inv1, f3 = o[j][3] * inv1;
        __nv_bfloat162 h0 = __floats2bfloat162_rn(f0, f1);
        __nv_bfloat162 h1 = __floats2bfloat162_rn(f2, f3);
        __nv_bfloat162 l0 = __floats2bfloat162_rn(f0 - __low2float(h0), f1 - __high2float(h0));
        __nv_bfloat162 l1 = __floats2bfloat162_rn(f2 - __low2float(h1), f3 - __high2float(h1));
        *(__nv_bfloat162*)(AOh + base0 + j * 8) = h0;
        *(__nv_bfloat162*)(AOl + base0 + j * 8) = l0;
        *(__nv_bfloat162*)(AOh + base1 + j * 8) = h1;
        *(__nv_bfloat162*)(AOl + base1 + j * 8) = l1;
    }
}

// ---------------- launch ----------------
extern "C" void kernel_launch(void* const* d_in, const int* in_sizes, int n_in,
                              void* d_out, int out_size) {
    const float* x    = (const float*)d_in[0];
    const float* wq_w = (const float*)d_in[2];
    const float* wq_A = (const float*)d_in[3];
    const float* wq_B = (const float*)d_in[4];
    const float* wk_w = (const float*)d_in[5];
    const float* wv_w = (const float*)d_in[6];
    const float* wv_A = (const float*)d_in[7];
    const float* wv_B = (const float*)d_in[8];
    const float* wo_w = (const float*)d_in[9];
    float* out = (float*)d_out;

    static bool attr_set = false;
    if (!attr_set) {
        cudaFuncSetAttribute(gemm_ts<0>,  cudaFuncAttributeMaxDynamicSharedMemorySize, SMEM_TOTAL);
        cudaFuncSetAttribute(gemm_ts<1>,  cudaFuncAttributeMaxDynamicSharedMemorySize, SMEM_TOTAL);
        cudaFuncSetAttribute(flash_mma, cudaFuncAttributeMaxDynamicSharedMemorySize, FSMEM);
        attr_set = true;
    }

    __nv_bfloat16 *Xh, *Xl, *Wh, *Wl, *WOh, *WOl;
    __nv_bfloat16 *Qh, *Ql, *Kh, *Kl, *Vh, *Vl, *AOh, *AOl;
    cudaGetSymbolAddress((void**)&Xh,  g_Xh);
    cudaGetSymbolAddress((void**)&Xl,  g_Xl);
    cudaGetSymbolAddress((void**)&Wh,  g_Wh);
    cudaGetSymbolAddress((void**)&Wl,  g_Wl);
    cudaGetSymbolAddress((void**)&WOh, g_WOh);
    cudaGetSymbolAddress((void**)&WOl, g_WOl);
    cudaGetSymbolAddress((void**)&Qh,  g_Qh);
    cudaGetSymbolAddress((void**)&Ql,  g_Ql);
    cudaGetSymbolAddress((void**)&Kh,  g_Kh);
    cudaGetSymbolAddress((void**)&Kl,  g_Kl);
    cudaGetSymbolAddress((void**)&Vh,  g_Vh);
    cudaGetSymbolAddress((void**)&Vl,  g_Vl);
    cudaGetSymbolAddress((void**)&AOh, g_AOh);
    cudaGetSymbolAddress((void**)&AOl, g_AOl);

    split_kernel<<<(MTOT * DD) / 256, 256>>>(x, Xh, Xl, MTOT * DD);
    prep_wcat<<<(NQKV * DD) / 256, 256>>>(wq_w, wq_A, wq_B, wk_w, wv_w, wv_A, wv_B, Wh, Wl);
    split_kernel<<<(DD * DD) / 256, 256>>>(wo_w, WOh, WOl, DD * DD);

    gemm_ts<1><<<dim3(NQKV / TN, MTOT / TM), 256, SMEM_TOTAL>>>(
        Xh, Xl, Wh, Wl, nullptr, NQKV, Qh, Ql, Kh, Kl, Vh, Vl);

    flash_mma<<<dim3(TT / 128, BB * HH), 256, FSMEM>>>(Qh, Ql, Kh, Kl, Vh, Vl, AOh, AOl);

    gemm_ts<0><<<dim3(DD / TN, MTOT / TM), 256, SMEM_TOTAL>>>(
        AOh, AOl, WOh, WOl, out, DD,
        nullptr, nullptr, nullptr, nullptr, nullptr, nullptr);
}

// round 6
// speedup vs baseline: 4.9934x; 1.5051x over previous
#include <cuda_runtime.h>
#include <cuda_fp16.h>
#include <cstdint>

#define DD    1024
#define TT    2048
#define BB    2
#define MTOT  4096
#define HH    16
#define DHD   64
#define RR    8
#define NQKV  3072

// ---- GEMM tiling: 128x128 CTA tile, 3 smem tiles/stage (Ah, Al, Bh), 3 stages
#define TM 128
#define TN 128
#define KSTEP 32
#define NK (DD / KSTEP)             // 32
#define ROWB 80
#define TILE_BYTES (128 * ROWB)     // 10240
#define STAGE_BYTES (3 * TILE_BYTES) // 30720
#define NSTAGE 3
#define SMEM_TOTAL (NSTAGE * STAGE_BYTES) // 92160

// ---- flash tiling: K,V single fp16; 3 stages
#define FROWB 144
#define FTILE (64 * FROWB)          // 9216
#define FSTAGE (2 * FTILE)          // 18432  (Kh, Vh)
#define FSMEM (3 * FSTAGE)          // 55296

// ---- scratch ----
__device__ __half g_Xh [MTOT * DD];
__device__ __half g_Xl [MTOT * DD];
__device__ __half g_Wh [NQKV * DD];
__device__ __half g_WOh[DD * DD];
__device__ __half g_Qh [MTOT * DD];
__device__ __half g_Ql [MTOT * DD];
__device__ __half g_Kh [MTOT * DD];
__device__ __half g_Vh [MTOT * DD];
__device__ __half g_AOh[MTOT * DD];
__device__ __half g_AOl[MTOT * DD];

// ---------------- PTX helpers ----------------
__device__ __forceinline__ uint32_t smem_u32(const void* p) {
    uint32_t a;
    asm("{ .reg .u64 t; cvta.to.shared.u64 t, %1; cvt.u32.u64 %0, t; }" : "=r"(a) : "l"(p));
    return a;
}
#define CP_ASYNC16(dst, src) \
    asm volatile("cp.async.cg.shared.global [%0], [%1], 16;" :: "r"(dst), "l"(src))
#define CP_COMMIT()   asm volatile("cp.async.commit_group;" ::: "memory")
#define CP_WAIT(n)    asm volatile("cp.async.wait_group %0;" :: "n"(n) : "memory")

__device__ __forceinline__ void ldsm4(uint32_t* r, uint32_t addr) {
    asm volatile("ldmatrix.sync.aligned.m8n8.x4.shared.b16 {%0,%1,%2,%3}, [%4];"
                 : "=r"(r[0]), "=r"(r[1]), "=r"(r[2]), "=r"(r[3]) : "r"(addr));
}
__device__ __forceinline__ void ldsm4t(uint32_t* r, uint32_t addr) {
    asm volatile("ldmatrix.sync.aligned.m8n8.x4.trans.shared.b16 {%0,%1,%2,%3}, [%4];"
                 : "=r"(r[0]), "=r"(r[1]), "=r"(r[2]), "=r"(r[3]) : "r"(addr));
}
__device__ __forceinline__ void mma16816(float* c, const uint32_t* a, const uint32_t* b) {
    asm volatile("mma.sync.aligned.m16n8k16.row.col.f32.f16.f16.f32 "
                 "{%0,%1,%2,%3}, {%4,%5,%6,%7}, {%8,%9}, {%0,%1,%2,%3};"
                 : "+f"(c[0]), "+f"(c[1]), "+f"(c[2]), "+f"(c[3])
                 : "r"(a[0]), "r"(a[1]), "r"(a[2]), "r"(a[3]), "r"(b[0]), "r"(b[1]));
}

// ---------------- prep kernels ----------------
__global__ void split_x(const float* __restrict__ s, __half* __restrict__ h,
                        __half* __restrict__ l, int n) {
    int i = blockIdx.x * blockDim.x + threadIdx.x;
    if (i >= n) return;
    float v = s[i];
    __half hb = __float2half_rn(v);
    h[i] = hb;
    l[i] = __float2half_rn(v - __half2float(hb));
}

__global__ void to_half(const float* __restrict__ s, __half* __restrict__ h, int n) {
    int i = blockIdx.x * blockDim.x + threadIdx.x;
    if (i < n) h[i] = __float2half_rn(s[i]);
}

// builds [3072,1024] concat weight = [Wq_eff ; Wk ; Wv_eff] in fp16
__global__ void prep_wcat(const float* __restrict__ wq, const float* __restrict__ qA,
                          const float* __restrict__ qB, const float* __restrict__ wk,
                          const float* __restrict__ wv, const float* __restrict__ vA,
                          const float* __restrict__ vB, __half* __restrict__ Wh) {
    int i = blockIdx.x * blockDim.x + threadIdx.x;
    if (i >= NQKV * DD) return;
    int o = i / DD, c = i % DD;
    float v;
    if (o < 1024) {
        v = wq[o * DD + c];
#pragma unroll
        for (int r = 0; r < RR; r++) v += 2.0f * qB[o * RR + r] * qA[r * DD + c];
    } else if (o < 2048) {
        v = wk[(o - 1024) * DD + c];
    } else {
        int oo = o - 2048;
        v = wv[oo * DD + c];
#pragma unroll
        for (int r = 0; r < RR; r++) v += 2.0f * vB[oo * RR + r] * vA[r * DD + c];
    }
    Wh[i] = __float2half_rn(v);
}

// ---------------- 2-term fp16 GEMM: C = (Ah+Al) @ Bh^T ----------------
__device__ __forceinline__ void load_stage(
    uint32_t stage_base,
    const __half* __restrict__ Ah, const __half* __restrict__ Al,
    const __half* __restrict__ Bh, int m0, int n0, int kc, int tid)
{
    const __half* srcs[3] = {Ah, Al, Bh};
#pragma unroll
    for (int t = 0; t < 3; t++) {
        const __half* base = srcs[t] + (size_t)(t < 2 ? m0 : n0) * DD + kc * KSTEP;
        uint32_t dst_tile = stage_base + t * TILE_BYTES;
#pragma unroll
        for (int i = 0; i < 2; i++) {
            int idx = tid + i * 256;
            int row = idx >> 2, c = idx & 3;
            CP_ASYNC16(dst_tile + row * ROWB + c * 16,
                       (const char*)(base + (size_t)row * DD) + c * 16);
        }
    }
}

// MODE 0: fp32 C.  MODE 1: fused QKV epilogue (Q split+scaled, K/V single fp16)
template<int MODE>
__global__ __launch_bounds__(256, 2) void gemm_ts(
    const __half* __restrict__ Ah, const __half* __restrict__ Al,
    const __half* __restrict__ Bh,
    float* __restrict__ C, int Ntot,
    __half* __restrict__ Qh, __half* __restrict__ Ql,
    __half* __restrict__ Kh, __half* __restrict__ Vh)
{
    extern __shared__ char smem[];
    uint32_t sb = smem_u32(smem);
    int tid = threadIdx.x;
    int wid = tid >> 5, lane = tid & 31;
    int wm = (wid & 3) * 32;
    int wn = (wid >> 2) * 64;
    int m0 = blockIdx.y * TM, n0 = blockIdx.x * TN;

    uint32_t aoff = (uint32_t)(wm + (lane & 15)) * ROWB + (lane >> 4) * 16;
    uint32_t boff = (uint32_t)(wn + (lane & 7) + ((lane >> 4) << 3)) * ROWB
                  + ((lane >> 3) & 1) * 16;

    float acc[2][8][4];
#pragma unroll
    for (int i = 0; i < 2; i++)
#pragma unroll
        for (int j = 0; j < 8; j++)
#pragma unroll
            for (int k = 0; k < 4; k++) acc[i][j][k] = 0.0f;

    load_stage(sb, Ah, Al, Bh, m0, n0, 0, tid);
    CP_COMMIT();
    load_stage(sb + STAGE_BYTES, Ah, Al, Bh, m0, n0, 1, tid);
    CP_COMMIT();

    int sidx = 0;
    for (int c = 0; c < NK; c++) {
        uint32_t st = sb + sidx * STAGE_BYTES;
        if (c + 1 < NK) { CP_WAIT(1); } else { CP_WAIT(0); }
        __syncthreads();                       // stage c ready; slot (c+2)%3 free
        if (c + 2 < NK) {
            int s2 = sidx + 2; if (s2 >= NSTAGE) s2 -= NSTAGE;
            load_stage(sb + s2 * STAGE_BYTES, Ah, Al, Bh, m0, n0, c + 2, tid);
            CP_COMMIT();
        }

        uint32_t baseAh = st + aoff;
        uint32_t baseAl = baseAh + TILE_BYTES;
        uint32_t baseBh = st + 2 * TILE_BYTES + boff;

#pragma unroll
        for (int kk = 0; kk < 2; kk++) {
            uint32_t koff = kk * 32;
            uint32_t ah[2][4], al[2][4], bh[4][4];
#pragma unroll
            for (int mt = 0; mt < 2; mt++) {
                ldsm4(ah[mt], baseAh + mt * 16 * ROWB + koff);
                ldsm4(al[mt], baseAl + mt * 16 * ROWB + koff);
            }
#pragma unroll
            for (int np = 0; np < 4; np++)
                ldsm4(bh[np], baseBh + np * 16 * ROWB + koff);
#pragma unroll
            for (int mt = 0; mt < 2; mt++)
#pragma unroll
                for (int np = 0; np < 4; np++) {
                    mma16816(acc[mt][np*2],   ah[mt], &bh[np][0]);
                    mma16816(acc[mt][np*2+1], ah[mt], &bh[np][2]);
                }
#pragma unroll
            for (int mt = 0; mt < 2; mt++)
#pragma unroll
                for (int np = 0; np < 4; np++) {
                    mma16816(acc[mt][np*2],   al[mt], &bh[np][0]);
                    mma16816(acc[mt][np*2+1], al[mt], &bh[np][2]);
                }
        }
        if (++sidx >= NSTAGE) sidx -= NSTAGE;
    }

    if (MODE == 0) {
        int rbase = m0 + wm + (lane >> 2);
        int cbase = n0 + wn + 2 * (lane & 3);
#pragma unroll
        for (int mt = 0; mt < 2; mt++)
#pragma unroll
            for (int nt = 0; nt < 8; nt++) {
                float* p0 = C + (size_t)(rbase + mt * 16) * Ntot + cbase + nt * 8;
                float* p1 = C + (size_t)(rbase + mt * 16 + 8) * Ntot + cbase + nt * 8;
                *(float2*)p0 = make_float2(acc[mt][nt][0], acc[mt][nt][1]);
                *(float2*)p1 = make_float2(acc[mt][nt][2], acc[mt][nt][3]);
            }
    } else {
        int colbase = n0 + wn;
        int sector = colbase >> 10;
        int h = (colbase & 1023) >> 6;
        int d0 = 2 * (lane & 3);
#pragma unroll
        for (int mt = 0; mt < 2; mt++) {
            int mrow0 = m0 + wm + (lane >> 2) + mt * 16;
            int mrow1 = mrow0 + 8;
            size_t base0 = ((size_t)((mrow0 >> 11) * HH + h) * TT + (mrow0 & 2047)) * DHD + d0;
            size_t base1 = ((size_t)((mrow1 >> 11) * HH + h) * TT + (mrow1 & 2047)) * DHD + d0;
            if (sector == 0) {
#pragma unroll
                for (int nt = 0; nt < 8; nt++) {
                    float f0 = acc[mt][nt][0] * 0.125f, f1 = acc[mt][nt][1] * 0.125f;
                    float f2 = acc[mt][nt][2] * 0.125f, f3 = acc[mt][nt][3] * 0.125f;
                    __half2 h0 = __floats2half2_rn(f0, f1);
                    __half2 h1 = __floats2half2_rn(f2, f3);
                    __half2 l0 = __floats2half2_rn(f0 - __low2float(h0), f1 - __high2float(h0));
                    __half2 l1 = __floats2half2_rn(f2 - __low2float(h1), f3 - __high2float(h1));
                    *(__half2*)(Qh + base0 + nt * 8) = h0;
                    *(__half2*)(Ql + base0 + nt * 8) = l0;
                    *(__half2*)(Qh + base1 + nt * 8) = h1;
                    *(__half2*)(Ql + base1 + nt * 8) = l1;
                }
            } else {
                __half* D = (sector == 1) ? Kh : Vh;
#pragma unroll
                for (int nt = 0; nt < 8; nt++) {
                    *(__half2*)(D + base0 + nt * 8) =
                        __floats2half2_rn(acc[mt][nt][0], acc[mt][nt][1]);
                    *(__half2*)(D + base1 + nt * 8) =
                        __floats2half2_rn(acc[mt][nt][2], acc[mt][nt][3]);
                }
            }
        }
    }
}

// ---------------- flash attention (fp16 2-term) ----------------
__device__ __forceinline__ void flash_load_kv(
    uint32_t st, const __half* __restrict__ Kh, const __half* __restrict__ Vh,
    int bh, int k0, int tid)
{
#pragma unroll
    for (int i = 0; i < 2; i++) {
        int idx = tid + i * 256;
        int row = idx >> 3, c = idx & 7;
        size_t krow = ((size_t)bh * TT + k0 + row) * DHD;
        CP_ASYNC16(st + row * FROWB + c * 16,         (const char*)(Kh + krow) + c * 16);
        CP_ASYNC16(st + FTILE + row * FROWB + c * 16, (const char*)(Vh + krow) + c * 16);
    }
}

__global__ __launch_bounds__(256) void flash_mma(
    const __half* __restrict__ Qh, const __half* __restrict__ Ql,
    const __half* __restrict__ Kh, const __half* __restrict__ Vh,
    __half* __restrict__ AOh, __half* __restrict__ AOl)
{
    extern __shared__ char smem[];
    uint32_t sb = smem_u32(smem);
    int tid = threadIdx.x, wid = tid >> 5, lane = tid & 31;
    int qblk = (TT / 128 - 1) - blockIdx.x;
    int bh = blockIdx.y;
    int q0 = qblk * 128;
    int wm = wid * 16;
    int nkt = 2 * qblk + 2;

    // ---- Q (hi+lo) into start of smem, consume to regs
#pragma unroll
    for (int i = 0; i < 4; i++) {
        int idx = tid + i * 256;
        int row = idx >> 3, c = idx & 7;
        size_t qrow = ((size_t)bh * TT + q0 + row) * DHD;
        CP_ASYNC16(sb + row * FROWB + c * 16,               (const char*)(Qh + qrow) + c * 16);
        CP_ASYNC16(sb + 128 * FROWB + row * FROWB + c * 16, (const char*)(Ql + qrow) + c * 16);
    }
    CP_COMMIT(); CP_WAIT(0);
    __syncthreads();
    uint32_t qaddr = sb + (uint32_t)(wm + (lane & 15)) * FROWB + (lane >> 4) * 16;
    uint32_t qfh[4][4], qfl[4][4];
#pragma unroll
    for (int s = 0; s < 4; s++) {
        ldsm4(qfh[s], qaddr + s * 32);
        ldsm4(qfl[s], qaddr + 128 * FROWB + s * 32);
    }
    __syncthreads();

    float o[8][4];
#pragma unroll
    for (int j = 0; j < 8; j++)
#pragma unroll
        for (int k = 0; k < 4; k++) o[j][k] = 0.0f;
    float mrow0 = -1e30f, mrow1 = -1e30f, lrow0 = 0.0f, lrow1 = 0.0f;

    flash_load_kv(sb, Kh, Vh, bh, 0, tid);
    CP_COMMIT();
    flash_load_kv(sb + FSTAGE, Kh, Vh, bh, 64, tid);
    CP_COMMIT();

    uint32_t bpat = (uint32_t)((lane & 7) + ((lane >> 4) << 3)) * FROWB + ((lane >> 3) & 1) * 16;
    uint32_t vpat = (uint32_t)(lane & 15) * FROWB + ((lane >> 4) << 4);

    int sidx = 0;
    for (int kt = 0; kt < nkt; kt++) {
        uint32_t st = sb + sidx * FSTAGE;
        if (kt + 1 < nkt) { CP_WAIT(1); } else { CP_WAIT(0); }
        __syncthreads();
        if (kt + 2 < nkt) {
            int s2 = sidx + 2; if (s2 >= 3) s2 -= 3;
            flash_load_kv(sb + s2 * FSTAGE, Kh, Vh, bh, (kt + 2) * 64, tid);
            CP_COMMIT();
        }

        // ---- S = Q K^T (2-term)
        float s[8][4];
#pragma unroll
        for (int j = 0; j < 8; j++)
#pragma unroll
            for (int k = 0; k < 4; k++) s[j][k] = 0.0f;
        uint32_t baseK = st + bpat;
#pragma unroll
        for (int ks = 0; ks < 4; ks++) {
            uint32_t koff = ks * 32;
            uint32_t kb[4][4];
#pragma unroll
            for (int np = 0; np < 4; np++)
                ldsm4(kb[np], baseK + np * 16 * FROWB + koff);
#pragma unroll
            for (int np = 0; np < 4; np++) {
                mma16816(s[np*2],   qfh[ks], &kb[np][0]);
                mma16816(s[np*2+1], qfh[ks], &kb[np][2]);
            }
#pragma unroll
            for (int np = 0; np < 4; np++) {
                mma16816(s[np*2],   qfl[ks], &kb[np][0]);
                mma16816(s[np*2+1], qfl[ks], &kb[np][2]);
            }
        }

        // ---- causal mask
        int row0 = q0 + wm + (lane >> 2);
        if (kt * 64 + 63 > row0) {
#pragma unroll
            for (int j = 0; j < 8; j++) {
                int colb = kt * 64 + j * 8 + 2 * (lane & 3);
                if (colb     > row0)     s[j][0] = -1e30f;
                if (colb + 1 > row0)     s[j][1] = -1e30f;
                if (colb     > row0 + 8) s[j][2] = -1e30f;
                if (colb + 1 > row0 + 8) s[j][3] = -1e30f;
            }
        }

        // ---- online softmax
        float mx0 = -1e30f, mx1 = -1e30f;
#pragma unroll
        for (int j = 0; j < 8; j++) {
            mx0 = fmaxf(mx0, fmaxf(s[j][0], s[j][1]));
            mx1 = fmaxf(mx1, fmaxf(s[j][2], s[j][3]));
        }
        mx0 = fmaxf(mx0, __shfl_xor_sync(0xffffffff, mx0, 1));
        mx0 = fmaxf(mx0, __shfl_xor_sync(0xffffffff, mx0, 2));
        mx1 = fmaxf(mx1, __shfl_xor_sync(0xffffffff, mx1, 1));
        mx1 = fmaxf(mx1, __shfl_xor_sync(0xffffffff, mx1, 2));
        float mn0 = fmaxf(mrow0, mx0), mn1 = fmaxf(mrow1, mx1);
        float cr0 = __expf(mrow0 - mn0), cr1 = __expf(mrow1 - mn1);
        lrow0 *= cr0; lrow1 *= cr1;
#pragma unroll
        for (int j = 0; j < 8; j++) {
            o[j][0] *= cr0; o[j][1] *= cr0;
            o[j][2] *= cr1; o[j][3] *= cr1;
        }
        mrow0 = mn0; mrow1 = mn1;

        float ls0 = 0.0f, ls1 = 0.0f;
        uint32_t ph[8][2], pl[8][2];
#pragma unroll
        for (int j = 0; j < 8; j++) {
            float p0 = __expf(s[j][0] - mn0), p1 = __expf(s[j][1] - mn0);
            float p2 = __expf(s[j][2] - mn1), p3 = __expf(s[j][3] - mn1);
            ls0 += p0 + p1; ls1 += p2 + p3;
            __half2 h0 = __floats2half2_rn(p0, p1);
            __half2 h1 = __floats2half2_rn(p2, p3);
            ph[j][0] = *(uint32_t*)&h0; ph[j][1] = *(uint32_t*)&h1;
            __half2 l0 = __floats2half2_rn(p0 - __low2float(h0), p1 - __high2float(h0));
            __half2 l1 = __floats2half2_rn(p2 - __low2float(h1), p3 - __high2float(h1));
            pl[j][0] = *(uint32_t*)&l0; pl[j][1] = *(uint32_t*)&l1;
        }
        ls0 += __shfl_xor_sync(0xffffffff, ls0, 1);
        ls0 += __shfl_xor_sync(0xffffffff, ls0, 2);
        ls1 += __shfl_xor_sync(0xffffffff, ls1, 1);
        ls1 += __shfl_xor_sync(0xffffffff, ls1, 2);
        lrow0 += ls0; lrow1 += ls1;

        // ---- O += P V (2-term; V via ldmatrix.trans)
        uint32_t baseV = st + FTILE + vpat;
#pragma unroll
        for (int ks = 0; ks < 4; ks++) {
            uint32_t ath[4] = { ph[2*ks][0], ph[2*ks][1], ph[2*ks+1][0], ph[2*ks+1][1] };
            uint32_t atl[4] = { pl[2*ks][0], pl[2*ks][1], pl[2*ks+1][0], pl[2*ks+1][1] };
            uint32_t roff = ks * 16 * FROWB;
            uint32_t vb[4][4];
#pragma unroll
            for (int np = 0; np < 4; np++)
                ldsm4t(vb[np], baseV + roff + np * 32);
#pragma unroll
            for (int np = 0; np < 4; np++) {
                mma16816(o[np*2],   ath, &vb[np][0]);
                mma16816(o[np*2+1], ath, &vb[np][2]);
            }
#pragma unroll
            for (int np = 0; np < 4; np++) {
                mma16816(o[np*2],   atl, &vb[np][0]);
                mma16816(o[np*2+1], atl, &vb[np][2]);
            }
        }
        if (++sidx >= 3) sidx -= 3;
    }

    // ---- epilogue: normalize + split fp16
    float inv0 = 1.0f / lrow0, inv1 = 1.0f / lrow1;
    int b = bh >> 4, h = bh & 15;
    int r0 = q0 + wm + (lane >> 2);
    size_t base0 = (size_t)(b * TT + r0) * DD + h * DHD + 2 * (lane & 3);
    size_t base1 = base0 + (size_t)8 * DD;
#pragma unroll
    for (int j = 0; j < 8; j++) {
        float f0 = o[j][0] * inv0, f1 = o[j][1] * inv0;
        float f2 = o[j][2] * inv1, f3 = o[j][3] * inv1;
        __half2 h0 = __floats2half2_rn(f0, f1);
        __half2 h1 = __floats2half2_rn(f2, f3);
        __half2 l0 = __floats2half2_rn(f0 - __low2float(h0), f1 - __high2float(h0));
        __half2 l1 = __floats2half2_rn(f2 - __low2float(h1), f3 - __high2float(h1));
        *(__half2*)(AOh + base0 + j * 8) = h0;
        *(__half2*)(AOl + base0 + j * 8) = l0;
        *(__half2*)(AOh + base1 + j * 8) = h1;
        *(__half2*)(AOl + base1 + j * 8) = l1;
    }
}

// ---------------- launch ----------------
extern "C" void kernel_launch(void* const* d_in, const int* in_sizes, int n_in,
                              void* d_out, int out_size) {
    const float* x    = (const float*)d_in[0];
    const float* wq_w = (const float*)d_in[2];
    const float* wq_A = (const float*)d_in[3];
    const float* wq_B = (const float*)d_in[4];
    const float* wk_w = (const float*)d_in[5];
    const float* wv_w = (const float*)d_in[6];
    const float* wv_A = (const float*)d_in[7];
    const float* wv_B = (const float*)d_in[8];
    const float* wo_w = (const float*)d_in[9];
    float* out = (float*)d_out;

    static bool attr_set = false;
    if (!attr_set) {
        cudaFuncSetAttribute(gemm_ts<0>, cudaFuncAttributeMaxDynamicSharedMemorySize, SMEM_TOTAL);
        cudaFuncSetAttribute(gemm_ts<1>, cudaFuncAttributeMaxDynamicSharedMemorySize, SMEM_TOTAL);
        cudaFuncSetAttribute(flash_mma,  cudaFuncAttributeMaxDynamicSharedMemorySize, FSMEM);
        attr_set = true;
    }

    __half *Xh, *Xl, *Wh, *WOh, *Qh, *Ql, *Kh, *Vh, *AOh, *AOl;
    cudaGetSymbolAddress((void**)&Xh,  g_Xh);
    cudaGetSymbolAddress((void**)&Xl,  g_Xl);
    cudaGetSymbolAddress((void**)&Wh,  g_Wh);
    cudaGetSymbolAddress((void**)&WOh, g_WOh);
    cudaGetSymbolAddress((void**)&Qh,  g_Qh);
    cudaGetSymbolAddress((void**)&Ql,  g_Ql);
    cudaGetSymbolAddress((void**)&Kh,  g_Kh);
    cudaGetSymbolAddress((void**)&Vh,  g_Vh);
    cudaGetSymbolAddress((void**)&AOh, g_AOh);
    cudaGetSymbolAddress((void**)&AOl, g_AOl);

    split_x<<<(MTOT * DD) / 256, 256>>>(x, Xh, Xl, MTOT * DD);
    prep_wcat<<<(NQKV * DD) / 256, 256>>>(wq_w, wq_A, wq_B, wk_w, wv_w, wv_A, wv_B, Wh);
    to_half<<<(DD * DD) / 256, 256>>>(wo_w, WOh, DD * DD);

    gemm_ts<1><<<dim3(NQKV / TN, MTOT / TM), 256, SMEM_TOTAL>>>(
        Xh, Xl, Wh, nullptr, NQKV, Qh, Ql, Kh, Vh);

    flash_mma<<<dim3(TT / 128, BB * HH), 256, FSMEM>>>(Qh, Ql, Kh, Vh, AOh, AOl);

    gemm_ts<0><<<dim3(DD / TN, MTOT / TM), 256, SMEM_TOTAL>>>(
        AOh, AOl, WOh, out, DD, nullptr, nullptr, nullptr, nullptr);
}

// round 7
// speedup vs baseline: 6.3256x; 1.2668x over previous
#include <cuda_runtime.h>
#include <cuda_fp16.h>
#include <cstdint>

#define DD    1024
#define TT    2048
#define BB    2
#define MTOT  4096
#define HH    16
#define DHD   64
#define RR    8
#define NQKV  3072

// ---- GEMM tiling: 128x128 CTA tile, 3 smem tiles/stage (Ah, Al, Bh), 3 stages
#define TM 128
#define TN 128
#define KSTEP 32
#define NK (DD / KSTEP)             // 32
#define ROWB 80
#define TILE_BYTES (128 * ROWB)     // 10240
#define STAGE_BYTES (3 * TILE_BYTES) // 30720
#define NSTAGE 3
#define SMEM_TOTAL (NSTAGE * STAGE_BYTES) // 92160

// ---- flash tiling: K,V single fp16; 3 stages
#define FROWB 144
#define FTILE (64 * FROWB)          // 9216
#define FSTAGE (2 * FTILE)          // 18432  (Kh, Vh)
#define FSMEM (3 * FSTAGE)          // 55296

// ---- scratch ----
__device__ __half g_Xh [MTOT * DD];
__device__ __half g_Xl [MTOT * DD];
__device__ __half g_Wh [NQKV * DD];
__device__ __half g_WOh[DD * DD];
__device__ __half g_Qh [MTOT * DD];
__device__ __half g_Ql [MTOT * DD];
__device__ __half g_Kh [MTOT * DD];
__device__ __half g_Vh [MTOT * DD];
__device__ __half g_AOh[MTOT * DD];

// ---------------- PTX helpers ----------------
__device__ __forceinline__ uint32_t smem_u32(const void* p) {
    uint32_t a;
    asm("{ .reg .u64 t; cvta.to.shared.u64 t, %1; cvt.u32.u64 %0, t; }" : "=r"(a) : "l"(p));
    return a;
}
#define CP_ASYNC16(dst, src) \
    asm volatile("cp.async.cg.shared.global [%0], [%1], 16;" :: "r"(dst), "l"(src))
#define CP_COMMIT()   asm volatile("cp.async.commit_group;" ::: "memory")
#define CP_WAIT(n)    asm volatile("cp.async.wait_group %0;" :: "n"(n) : "memory")

__device__ __forceinline__ void ldsm4(uint32_t* r, uint32_t addr) {
    asm volatile("ldmatrix.sync.aligned.m8n8.x4.shared.b16 {%0,%1,%2,%3}, [%4];"
                 : "=r"(r[0]), "=r"(r[1]), "=r"(r[2]), "=r"(r[3]) : "r"(addr));
}
__device__ __forceinline__ void ldsm4t(uint32_t* r, uint32_t addr) {
    asm volatile("ldmatrix.sync.aligned.m8n8.x4.trans.shared.b16 {%0,%1,%2,%3}, [%4];"
                 : "=r"(r[0]), "=r"(r[1]), "=r"(r[2]), "=r"(r[3]) : "r"(addr));
}
__device__ __forceinline__ void mma16816(float* c, const uint32_t* a, const uint32_t* b) {
    asm volatile("mma.sync.aligned.m16n8k16.row.col.f32.f16.f16.f32 "
                 "{%0,%1,%2,%3}, {%4,%5,%6,%7}, {%8,%9}, {%0,%1,%2,%3};"
                 : "+f"(c[0]), "+f"(c[1]), "+f"(c[2]), "+f"(c[3])
                 : "r"(a[0]), "r"(a[1]), "r"(a[2]), "r"(a[3]), "r"(b[0]), "r"(b[1]));
}

// ---------------- prep kernels ----------------
__global__ void split_x(const float* __restrict__ s, __half* __restrict__ h,
                        __half* __restrict__ l, int n) {
    int i = blockIdx.x * blockDim.x + threadIdx.x;
    if (i >= n) return;
    float v = s[i];
    __half hb = __float2half_rn(v);
    h[i] = hb;
    l[i] = __float2half_rn(v - __half2float(hb));
}

__global__ void to_half(const float* __restrict__ s, __half* __restrict__ h, int n) {
    int i = blockIdx.x * blockDim.x + threadIdx.x;
    if (i < n) h[i] = __float2half_rn(s[i]);
}

// builds [3072,1024] concat weight = [Wq_eff ; Wk ; Wv_eff] in fp16
__global__ void prep_wcat(const float* __restrict__ wq, const float* __restrict__ qA,
                          const float* __restrict__ qB, const float* __restrict__ wk,
                          const float* __restrict__ wv, const float* __restrict__ vA,
                          const float* __restrict__ vB, __half* __restrict__ Wh) {
    int i = blockIdx.x * blockDim.x + threadIdx.x;
    if (i >= NQKV * DD) return;
    int o = i / DD, c = i % DD;
    float v;
    if (o < 1024) {
        v = wq[o * DD + c];
#pragma unroll
        for (int r = 0; r < RR; r++) v += 2.0f * qB[o * RR + r] * qA[r * DD + c];
    } else if (o < 2048) {
        v = wk[(o - 1024) * DD + c];
    } else {
        int oo = o - 2048;
        v = wv[oo * DD + c];
#pragma unroll
        for (int r = 0; r < RR; r++) v += 2.0f * vB[oo * RR + r] * vA[r * DD + c];
    }
    Wh[i] = __float2half_rn(v);
}

// ---------------- fp16 GEMM: C = (Ah [+ Al]) @ Bh^T ----------------
__device__ __forceinline__ void load_stage(
    uint32_t stage_base,
    const __half* __restrict__ Ah, const __half* __restrict__ Al,
    const __half* __restrict__ Bh, int m0, int n0, int kc, int tid, bool use_lo)
{
#pragma unroll
    for (int t = 0; t < 3; t++) {
        if (t == 1 && !use_lo) continue;
        const __half* src = (t == 0) ? Ah : (t == 1) ? Al : Bh;
        const __half* base = src + (size_t)(t < 2 ? m0 : n0) * DD + kc * KSTEP;
        uint32_t dst_tile = stage_base + t * TILE_BYTES;
#pragma unroll
        for (int i = 0; i < 2; i++) {
            int idx = tid + i * 256;
            int row = idx >> 2, c = idx & 3;
            CP_ASYNC16(dst_tile + row * ROWB + c * 16,
                       (const char*)(base + (size_t)row * DD) + c * 16);
        }
    }
}

// MODE 0: fp32 C, single-term A.  MODE 1: fused QKV epilogue; lo-term only for Q sector
template<int MODE>
__global__ __launch_bounds__(256, 2) void gemm_ts(
    const __half* __restrict__ Ah, const __half* __restrict__ Al,
    const __half* __restrict__ Bh,
    float* __restrict__ C, int Ntot,
    __half* __restrict__ Qh, __half* __restrict__ Ql,
    __half* __restrict__ Kh, __half* __restrict__ Vh)
{
    extern __shared__ char smem[];
    uint32_t sb = smem_u32(smem);
    int tid = threadIdx.x;
    int wid = tid >> 5, lane = tid & 31;
    int wm = (wid & 3) * 32;
    int wn = (wid >> 2) * 64;
    int m0 = blockIdx.y * TM, n0 = blockIdx.x * TN;
    const bool use_lo = (MODE == 1) && (n0 < 1024);   // lo correction only for Q sector

    uint32_t aoff = (uint32_t)(wm + (lane & 15)) * ROWB + (lane >> 4) * 16;
    uint32_t boff = (uint32_t)(wn + (lane & 7) + ((lane >> 4) << 3)) * ROWB
                  + ((lane >> 3) & 1) * 16;

    float acc[2][8][4];
#pragma unroll
    for (int i = 0; i < 2; i++)
#pragma unroll
        for (int j = 0; j < 8; j++)
#pragma unroll
            for (int k = 0; k < 4; k++) acc[i][j][k] = 0.0f;

    load_stage(sb, Ah, Al, Bh, m0, n0, 0, tid, use_lo);
    CP_COMMIT();
    load_stage(sb + STAGE_BYTES, Ah, Al, Bh, m0, n0, 1, tid, use_lo);
    CP_COMMIT();

    int sidx = 0;
    for (int c = 0; c < NK; c++) {
        uint32_t st = sb + sidx * STAGE_BYTES;
        if (c + 1 < NK) { CP_WAIT(1); } else { CP_WAIT(0); }
        __syncthreads();
        if (c + 2 < NK) {
            int s2 = sidx + 2; if (s2 >= NSTAGE) s2 -= NSTAGE;
            load_stage(sb + s2 * STAGE_BYTES, Ah, Al, Bh, m0, n0, c + 2, tid, use_lo);
            CP_COMMIT();
        }

        uint32_t baseAh = st + aoff;
        uint32_t baseAl = baseAh + TILE_BYTES;
        uint32_t baseBh = st + 2 * TILE_BYTES + boff;

#pragma unroll
        for (int kk = 0; kk < 2; kk++) {
            uint32_t koff = kk * 32;
            uint32_t ah[2][4], bh[4][4];
#pragma unroll
            for (int mt = 0; mt < 2; mt++)
                ldsm4(ah[mt], baseAh + mt * 16 * ROWB + koff);
#pragma unroll
            for (int np = 0; np < 4; np++)
                ldsm4(bh[np], baseBh + np * 16 * ROWB + koff);
#pragma unroll
            for (int mt = 0; mt < 2; mt++)
#pragma unroll
                for (int np = 0; np < 4; np++) {
                    mma16816(acc[mt][np*2],   ah[mt], &bh[np][0]);
                    mma16816(acc[mt][np*2+1], ah[mt], &bh[np][2]);
                }
            if (use_lo) {
                uint32_t al[2][4];
#pragma unroll
                for (int mt = 0; mt < 2; mt++)
                    ldsm4(al[mt], baseAl + mt * 16 * ROWB + koff);
#pragma unroll
                for (int mt = 0; mt < 2; mt++)
#pragma unroll
                    for (int np = 0; np < 4; np++) {
                        mma16816(acc[mt][np*2],   al[mt], &bh[np][0]);
                        mma16816(acc[mt][np*2+1], al[mt], &bh[np][2]);
                    }
            }
        }
        if (++sidx >= NSTAGE) sidx -= NSTAGE;
    }

    if (MODE == 0) {
        int rbase = m0 + wm + (lane >> 2);
        int cbase = n0 + wn + 2 * (lane & 3);
#pragma unroll
        for (int mt = 0; mt < 2; mt++)
#pragma unroll
            for (int nt = 0; nt < 8; nt++) {
                float* p0 = C + (size_t)(rbase + mt * 16) * Ntot + cbase + nt * 8;
                float* p1 = C + (size_t)(rbase + mt * 16 + 8) * Ntot + cbase + nt * 8;
                *(float2*)p0 = make_float2(acc[mt][nt][0], acc[mt][nt][1]);
                *(float2*)p1 = make_float2(acc[mt][nt][2], acc[mt][nt][3]);
            }
    } else {
        int colbase = n0 + wn;
        int sector = colbase >> 10;
        int h = (colbase & 1023) >> 6;
        int d0 = 2 * (lane & 3);
#pragma unroll
        for (int mt = 0; mt < 2; mt++) {
            int mrow0 = m0 + wm + (lane >> 2) + mt * 16;
            int mrow1 = mrow0 + 8;
            size_t base0 = ((size_t)((mrow0 >> 11) * HH + h) * TT + (mrow0 & 2047)) * DHD + d0;
            size_t base1 = ((size_t)((mrow1 >> 11) * HH + h) * TT + (mrow1 & 2047)) * DHD + d0;
            if (sector == 0) {
#pragma unroll
                for (int nt = 0; nt < 8; nt++) {
                    float f0 = acc[mt][nt][0] * 0.125f, f1 = acc[mt][nt][1] * 0.125f;
                    float f2 = acc[mt][nt][2] * 0.125f, f3 = acc[mt][nt][3] * 0.125f;
                    __half2 h0 = __floats2half2_rn(f0, f1);
                    __half2 h1 = __floats2half2_rn(f2, f3);
                    __half2 l0 = __floats2half2_rn(f0 - __low2float(h0), f1 - __high2float(h0));
                    __half2 l1 = __floats2half2_rn(f2 - __low2float(h1), f3 - __high2float(h1));
                    *(__half2*)(Qh + base0 + nt * 8) = h0;
                    *(__half2*)(Ql + base0 + nt * 8) = l0;
                    *(__half2*)(Qh + base1 + nt * 8) = h1;
                    *(__half2*)(Ql + base1 + nt * 8) = l1;
                }
            } else {
                __half* D = (sector == 1) ? Kh : Vh;
#pragma unroll
                for (int nt = 0; nt < 8; nt++) {
                    *(__half2*)(D + base0 + nt * 8) =
                        __floats2half2_rn(acc[mt][nt][0], acc[mt][nt][1]);
                    *(__half2*)(D + base1 + nt * 8) =
                        __floats2half2_rn(acc[mt][nt][2], acc[mt][nt][3]);
                }
            }
        }
    }
}

// ---------------- flash attention (Q 2-term, P single) ----------------
__device__ __forceinline__ void flash_load_kv(
    uint32_t st, const __half* __restrict__ Kh, const __half* __restrict__ Vh,
    int bh, int k0, int tid)
{
#pragma unroll
    for (int i = 0; i < 2; i++) {
        int idx = tid + i * 256;
        int row = idx >> 3, c = idx & 7;
        size_t krow = ((size_t)bh * TT + k0 + row) * DHD;
        CP_ASYNC16(st + row * FROWB + c * 16,         (const char*)(Kh + krow) + c * 16);
        CP_ASYNC16(st + FTILE + row * FROWB + c * 16, (const char*)(Vh + krow) + c * 16);
    }
}

__global__ __launch_bounds__(256) void flash_mma(
    const __half* __restrict__ Qh, const __half* __restrict__ Ql,
    const __half* __restrict__ Kh, const __half* __restrict__ Vh,
    __half* __restrict__ AOh)
{
    extern __shared__ char smem[];
    uint32_t sb = smem_u32(smem);
    int tid = threadIdx.x, wid = tid >> 5, lane = tid & 31;
    int qblk = (TT / 128 - 1) - blockIdx.x;
    int bh = blockIdx.y;
    int q0 = qblk * 128;
    int wm = wid * 16;
    int nkt = 2 * qblk + 2;

#pragma unroll
    for (int i = 0; i < 4; i++) {
        int idx = tid + i * 256;
        int row = idx >> 3, c = idx & 7;
        size_t qrow = ((size_t)bh * TT + q0 + row) * DHD;
        CP_ASYNC16(sb + row * FROWB + c * 16,               (const char*)(Qh + qrow) + c * 16);
        CP_ASYNC16(sb + 128 * FROWB + row * FROWB + c * 16, (const char*)(Ql + qrow) + c * 16);
    }
    CP_COMMIT(); CP_WAIT(0);
    __syncthreads();
    uint32_t qaddr = sb + (uint32_t)(wm + (lane & 15)) * FROWB + (lane >> 4) * 16;
    uint32_t qfh[4][4], qfl[4][4];
#pragma unroll
    for (int s = 0; s < 4; s++) {
        ldsm4(qfh[s], qaddr + s * 32);
        ldsm4(qfl[s], qaddr + 128 * FROWB + s * 32);
    }
    __syncthreads();

    float o[8][4];
#pragma unroll
    for (int j = 0; j < 8; j++)
#pragma unroll
        for (int k = 0; k < 4; k++) o[j][k] = 0.0f;
    float mrow0 = -1e30f, mrow1 = -1e30f, lrow0 = 0.0f, lrow1 = 0.0f;

    flash_load_kv(sb, Kh, Vh, bh, 0, tid);
    CP_COMMIT();
    flash_load_kv(sb + FSTAGE, Kh, Vh, bh, 64, tid);
    CP_COMMIT();

    uint32_t bpat = (uint32_t)((lane & 7) + ((lane >> 4) << 3)) * FROWB + ((lane >> 3) & 1) * 16;
    uint32_t vpat = (uint32_t)(lane & 15) * FROWB + ((lane >> 4) << 4);

    int sidx = 0;
    for (int kt = 0; kt < nkt; kt++) {
        uint32_t st = sb + sidx * FSTAGE;
        if (kt + 1 < nkt) { CP_WAIT(1); } else { CP_WAIT(0); }
        __syncthreads();
        if (kt + 2 < nkt) {
            int s2 = sidx + 2; if (s2 >= 3) s2 -= 3;
            flash_load_kv(sb + s2 * FSTAGE, Kh, Vh, bh, (kt + 2) * 64, tid);
            CP_COMMIT();
        }

        // ---- S = Q K^T (Q 2-term)
        float s[8][4];
#pragma unroll
        for (int j = 0; j < 8; j++)
#pragma unroll
            for (int k = 0; k < 4; k++) s[j][k] = 0.0f;
        uint32_t baseK = st + bpat;
#pragma unroll
        for (int ks = 0; ks < 4; ks++) {
            uint32_t koff = ks * 32;
            uint32_t kb[4][4];
#pragma unroll
            for (int np = 0; np < 4; np++)
                ldsm4(kb[np], baseK + np * 16 * FROWB + koff);
#pragma unroll
            for (int np = 0; np < 4; np++) {
                mma16816(s[np*2],   qfh[ks], &kb[np][0]);
                mma16816(s[np*2+1], qfh[ks], &kb[np][2]);
            }
#pragma unroll
            for (int np = 0; np < 4; np++) {
                mma16816(s[np*2],   qfl[ks], &kb[np][0]);
                mma16816(s[np*2+1], qfl[ks], &kb[np][2]);
            }
        }

        // ---- causal mask
        int row0 = q0 + wm + (lane >> 2);
        if (kt * 64 + 63 > row0) {
#pragma unroll
            for (int j = 0; j < 8; j++) {
                int colb = kt * 64 + j * 8 + 2 * (lane & 3);
                if (colb     > row0)     s[j][0] = -1e30f;
                if (colb + 1 > row0)     s[j][1] = -1e30f;
                if (colb     > row0 + 8) s[j][2] = -1e30f;
                if (colb + 1 > row0 + 8) s[j][3] = -1e30f;
            }
        }

        // ---- online softmax
        float mx0 = -1e30f, mx1 = -1e30f;
#pragma unroll
        for (int j = 0; j < 8; j++) {
            mx0 = fmaxf(mx0, fmaxf(s[j][0], s[j][1]));
            mx1 = fmaxf(mx1, fmaxf(s[j][2], s[j][3]));
        }
        mx0 = fmaxf(mx0, __shfl_xor_sync(0xffffffff, mx0, 1));
        mx0 = fmaxf(mx0, __shfl_xor_sync(0xffffffff, mx0, 2));
        mx1 = fmaxf(mx1, __shfl_xor_sync(0xffffffff, mx1, 1));
        mx1 = fmaxf(mx1, __shfl_xor_sync(0xffffffff, mx1, 2));
        float mn0 = fmaxf(mrow0, mx0), mn1 = fmaxf(mrow1, mx1);
        float cr0 = __expf(mrow0 - mn0), cr1 = __expf(mrow1 - mn1);
        lrow0 *= cr0; lrow1 *= cr1;
#pragma unroll
        for (int j = 0; j < 8; j++) {
            o[j][0] *= cr0; o[j][1] *= cr0;
            o[j][2] *= cr1; o[j][3] *= cr1;
        }
        mrow0 = mn0; mrow1 = mn1;

        float ls0 = 0.0f, ls1 = 0.0f;
        uint32_t ph[8][2];
#pragma unroll
        for (int j = 0; j < 8; j++) {
            float p0 = __expf(s[j][0] - mn0), p1 = __expf(s[j][1] - mn0);
            float p2 = __expf(s[j][2] - mn1), p3 = __expf(s[j][3] - mn1);
            ls0 += p0 + p1; ls1 += p2 + p3;
            __half2 h0 = __floats2half2_rn(p0, p1);
            __half2 h1 = __floats2half2_rn(p2, p3);
            ph[j][0] = *(uint32_t*)&h0; ph[j][1] = *(uint32_t*)&h1;
        }
        ls0 += __shfl_xor_sync(0xffffffff, ls0, 1);
        ls0 += __shfl_xor_sync(0xffffffff, ls0, 2);
        ls1 += __shfl_xor_sync(0xffffffff, ls1, 1);
        ls1 += __shfl_xor_sync(0xffffffff, ls1, 2);
        lrow0 += ls0; lrow1 += ls1;

        // ---- O += P V (single P; V via ldmatrix.trans)
        uint32_t baseV = st + FTILE + vpat;
#pragma unroll
        for (int ks = 0; ks < 4; ks++) {
            uint32_t ath[4] = { ph[2*ks][0], ph[2*ks][1], ph[2*ks+1][0], ph[2*ks+1][1] };
            uint32_t roff = ks * 16 * FROWB;
            uint32_t vb[4][4];
#pragma unroll
            for (int np = 0; np < 4; np++)
                ldsm4t(vb[np], baseV + roff + np * 32);
#pragma unroll
            for (int np = 0; np < 4; np++) {
                mma16816(o[np*2],   ath, &vb[np][0]);
                mma16816(o[np*2+1], ath, &vb[np][2]);
            }
        }
        if (++sidx >= 3) sidx -= 3;
    }

    // ---- epilogue: normalize, single fp16 AO
    float inv0 = 1.0f / lrow0, inv1 = 1.0f / lrow1;
    int b = bh >> 4, h = bh & 15;
    int r0 = q0 + wm + (lane >> 2);
    size_t base0 = (size_t)(b * TT + r0) * DD + h * DHD + 2 * (lane & 3);
    size_t base1 = base0 + (size_t)8 * DD;
#pragma unroll
    for (int j = 0; j < 8; j++) {
        *(__half2*)(AOh + base0 + j * 8) = __floats2half2_rn(o[j][0] * inv0, o[j][1] * inv0);
        *(__half2*)(AOh + base1 + j * 8) = __floats2half2_rn(o[j][2] * inv1, o[j][3] * inv1);
    }
}

// ---------------- launch ----------------
extern "C" void kernel_launch(void* const* d_in, const int* in_sizes, int n_in,
                              void* d_out, int out_size) {
    const float* x    = (const float*)d_in[0];
    const float* wq_w = (const float*)d_in[2];
    const float* wq_A = (const float*)d_in[3];
    const float* wq_B = (const float*)d_in[4];
    const float* wk_w = (const float*)d_in[5];
    const float* wv_w = (const float*)d_in[6];
    const float* wv_A = (const float*)d_in[7];
    const float* wv_B = (const float*)d_in[8];
    const float* wo_w = (const float*)d_in[9];
    float* out = (float*)d_out;

    static bool attr_set = false;
    if (!attr_set) {
        cudaFuncSetAttribute(gemm_ts<0>, cudaFuncAttributeMaxDynamicSharedMemorySize, SMEM_TOTAL);
        cudaFuncSetAttribute(gemm_ts<1>, cudaFuncAttributeMaxDynamicSharedMemorySize, SMEM_TOTAL);
        cudaFuncSetAttribute(flash_mma,  cudaFuncAttributeMaxDynamicSharedMemorySize, FSMEM);
        attr_set = true;
    }

    __half *Xh, *Xl, *Wh, *WOh, *Qh, *Ql, *Kh, *Vh, *AOh;
    cudaGetSymbolAddress((void**)&Xh,  g_Xh);
    cudaGetSymbolAddress((void**)&Xl,  g_Xl);
    cudaGetSymbolAddress((void**)&Wh,  g_Wh);
    cudaGetSymbolAddress((void**)&WOh, g_WOh);
    cudaGetSymbolAddress((void**)&Qh,  g_Qh);
    cudaGetSymbolAddress((void**)&Ql,  g_Ql);
    cudaGetSymbolAddress((void**)&Kh,  g_Kh);
    cudaGetSymbolAddress((void**)&Vh,  g_Vh);
    cudaGetSymbolAddress((void**)&AOh, g_AOh);

    split_x<<<(MTOT * DD) / 256, 256>>>(x, Xh, Xl, MTOT * DD);
    prep_wcat<<<(NQKV * DD) / 256, 256>>>(wq_w, wq_A, wq_B, wk_w, wv_w, wv_A, wv_B, Wh);
    to_half<<<(DD * DD) / 256, 256>>>(wo_w, WOh, DD * DD);

    gemm_ts<1><<<dim3(NQKV / TN, MTOT / TM), 256, SMEM_TOTAL>>>(
        Xh, Xl, Wh, nullptr, NQKV, Qh, Ql, Kh, Vh);

    flash_mma<<<dim3(TT / 128, BB * HH), 256, FSMEM>>>(Qh, Ql, Kh, Vh, AOh);

    gemm_ts<0><<<dim3(DD / TN, MTOT / TM), 256, SMEM_TOTAL>>>(
        AOh, nullptr, WOh, out, DD, nullptr, nullptr, nullptr, nullptr);
}

// round 8
// speedup vs baseline: 7.5117x; 1.1875x over previous
#include <cuda_runtime.h>
#include <cuda_fp16.h>
#include <cstdint>

#define DD    1024
#define TT    2048
#define BB    2
#define MTOT  4096
#define HH    16
#define DHD   64
#define RR    8
#define NQKV  3072

// ---- GEMM tiling: 128x128 CTA tile, 2 smem tiles/stage (A, B), 3 stages
#define TM 128
#define TN 128
#define KSTEP 32
#define NK (DD / KSTEP)              // 32
#define ROWB 80
#define TILE_BYTES (128 * ROWB)      // 10240
#define STAGE_BYTES (2 * TILE_BYTES) // 20480
#define NSTAGE 3
#define SMEM_TOTAL (NSTAGE * STAGE_BYTES) // 61440

// ---- flash tiling: K,V single fp16; 3 stages
#define FROWB 144
#define FTILE (64 * FROWB)          // 9216
#define FSTAGE (2 * FTILE)          // 18432  (Kh, Vh)
#define FSMEM (3 * FSTAGE)          // 55296

// ---- scratch ----
__device__ __half g_Xh [MTOT * DD];
__device__ __half g_Wh [NQKV * DD];
__device__ __half g_WOh[DD * DD];
__device__ __half g_Qh [MTOT * DD];
__device__ __half g_Kh [MTOT * DD];
__device__ __half g_Vh [MTOT * DD];
__device__ __half g_AOh[MTOT * DD];

// ---------------- PTX helpers ----------------
__device__ __forceinline__ uint32_t smem_u32(const void* p) {
    uint32_t a;
    asm("{ .reg .u64 t; cvta.to.shared.u64 t, %1; cvt.u32.u64 %0, t; }" : "=r"(a) : "l"(p));
    return a;
}
#define CP_ASYNC16(dst, src) \
    asm volatile("cp.async.cg.shared.global [%0], [%1], 16;" :: "r"(dst), "l"(src))
#define CP_COMMIT()   asm volatile("cp.async.commit_group;" ::: "memory")
#define CP_WAIT(n)    asm volatile("cp.async.wait_group %0;" :: "n"(n) : "memory")

__device__ __forceinline__ void ldsm4(uint32_t* r, uint32_t addr) {
    asm volatile("ldmatrix.sync.aligned.m8n8.x4.shared.b16 {%0,%1,%2,%3}, [%4];"
                 : "=r"(r[0]), "=r"(r[1]), "=r"(r[2]), "=r"(r[3]) : "r"(addr));
}
__device__ __forceinline__ void ldsm4t(uint32_t* r, uint32_t addr) {
    asm volatile("ldmatrix.sync.aligned.m8n8.x4.trans.shared.b16 {%0,%1,%2,%3}, [%4];"
                 : "=r"(r[0]), "=r"(r[1]), "=r"(r[2]), "=r"(r[3]) : "r"(addr));
}
__device__ __forceinline__ void mma16816(float* c, const uint32_t* a, const uint32_t* b) {
    asm volatile("mma.sync.aligned.m16n8k16.row.col.f32.f16.f16.f32 "
                 "{%0,%1,%2,%3}, {%4,%5,%6,%7}, {%8,%9}, {%0,%1,%2,%3};"
                 : "+f"(c[0]), "+f"(c[1]), "+f"(c[2]), "+f"(c[3])
                 : "r"(a[0]), "r"(a[1]), "r"(a[2]), "r"(a[3]), "r"(b[0]), "r"(b[1]));
}

// ---------------- prep kernels ----------------
__global__ void to_half(const float* __restrict__ s, __half* __restrict__ h, int n) {
    int i = blockIdx.x * blockDim.x + threadIdx.x;
    if (i < n) h[i] = __float2half_rn(s[i]);
}

// builds [3072,1024] concat weight = [Wq_eff ; Wk ; Wv_eff] in fp16
__global__ void prep_wcat(const float* __restrict__ wq, const float* __restrict__ qA,
                          const float* __restrict__ qB, const float* __restrict__ wk,
                          const float* __restrict__ wv, const float* __restrict__ vA,
                          const float* __restrict__ vB, __half* __restrict__ Wh) {
    int i = blockIdx.x * blockDim.x + threadIdx.x;
    if (i >= NQKV * DD) return;
    int o = i / DD, c = i % DD;
    float v;
    if (o < 1024) {
        v = wq[o * DD + c];
#pragma unroll
        for (int r = 0; r < RR; r++) v += 2.0f * qB[o * RR + r] * qA[r * DD + c];
    } else if (o < 2048) {
        v = wk[(o - 1024) * DD + c];
    } else {
        int oo = o - 2048;
        v = wv[oo * DD + c];
#pragma unroll
        for (int r = 0; r < RR; r++) v += 2.0f * vB[oo * RR + r] * vA[r * DD + c];
    }
    Wh[i] = __float2half_rn(v);
}

// ---------------- single-term fp16 GEMM: C = A @ B^T ----------------
__device__ __forceinline__ void load_stage(
    uint32_t stage_base, const __half* __restrict__ A, const __half* __restrict__ B,
    int m0, int n0, int kc, int tid)
{
#pragma unroll
    for (int t = 0; t < 2; t++) {
        const __half* base = (t == 0 ? A : B) + (size_t)(t == 0 ? m0 : n0) * DD + kc * KSTEP;
        uint32_t dst_tile = stage_base + t * TILE_BYTES;
#pragma unroll
        for (int i = 0; i < 2; i++) {
            int idx = tid + i * 256;
            int row = idx >> 2, c = idx & 3;
            CP_ASYNC16(dst_tile + row * ROWB + c * 16,
                       (const char*)(base + (size_t)row * DD) + c * 16);
        }
    }
}

// MODE 0: fp32 C.  MODE 1: fused QKV epilogue (per-head fp16, Q scaled)
template<int MODE>
__global__ __launch_bounds__(256, 2) void gemm_ts(
    const __half* __restrict__ A, const __half* __restrict__ B,
    float* __restrict__ C, int Ntot,
    __half* __restrict__ Qh, __half* __restrict__ Kh, __half* __restrict__ Vh)
{
    extern __shared__ char smem[];
    uint32_t sb = smem_u32(smem);
    int tid = threadIdx.x;
    int wid = tid >> 5, lane = tid & 31;
    int wm = (wid & 3) * 32;
    int wn = (wid >> 2) * 64;
    int m0 = blockIdx.y * TM, n0 = blockIdx.x * TN;

    uint32_t aoff = (uint32_t)(wm + (lane & 15)) * ROWB + (lane >> 4) * 16;
    uint32_t boff = (uint32_t)(wn + (lane & 7) + ((lane >> 4) << 3)) * ROWB
                  + ((lane >> 3) & 1) * 16;

    float acc[2][8][4];
#pragma unroll
    for (int i = 0; i < 2; i++)
#pragma unroll
        for (int j = 0; j < 8; j++)
#pragma unroll
            for (int k = 0; k < 4; k++) acc[i][j][k] = 0.0f;

    load_stage(sb, A, B, m0, n0, 0, tid);
    CP_COMMIT();
    load_stage(sb + STAGE_BYTES, A, B, m0, n0, 1, tid);
    CP_COMMIT();

    int sidx = 0;
    for (int c = 0; c < NK; c++) {
        uint32_t st = sb + sidx * STAGE_BYTES;
        if (c + 1 < NK) { CP_WAIT(1); } else { CP_WAIT(0); }
        __syncthreads();
        if (c + 2 < NK) {
            int s2 = sidx + 2; if (s2 >= NSTAGE) s2 -= NSTAGE;
            load_stage(sb + s2 * STAGE_BYTES, A, B, m0, n0, c + 2, tid);
            CP_COMMIT();
        }

        uint32_t baseA = st + aoff;
        uint32_t baseB = st + TILE_BYTES + boff;

#pragma unroll
        for (int kk = 0; kk < 2; kk++) {
            uint32_t koff = kk * 32;
            uint32_t a[2][4], b[4][4];
#pragma unroll
            for (int mt = 0; mt < 2; mt++)
                ldsm4(a[mt], baseA + mt * 16 * ROWB + koff);
#pragma unroll
            for (int np = 0; np < 4; np++)
                ldsm4(b[np], baseB + np * 16 * ROWB + koff);
#pragma unroll
            for (int mt = 0; mt < 2; mt++)
#pragma unroll
                for (int np = 0; np < 4; np++) {
                    mma16816(acc[mt][np*2],   a[mt], &b[np][0]);
                    mma16816(acc[mt][np*2+1], a[mt], &b[np][2]);
                }
        }
        if (++sidx >= NSTAGE) sidx -= NSTAGE;
    }

    if (MODE == 0) {
        int rbase = m0 + wm + (lane >> 2);
        int cbase = n0 + wn + 2 * (lane & 3);
#pragma unroll
        for (int mt = 0; mt < 2; mt++)
#pragma unroll
            for (int nt = 0; nt < 8; nt++) {
                float* p0 = C + (size_t)(rbase + mt * 16) * Ntot + cbase + nt * 8;
                float* p1 = C + (size_t)(rbase + mt * 16 + 8) * Ntot + cbase + nt * 8;
                *(float2*)p0 = make_float2(acc[mt][nt][0], acc[mt][nt][1]);
                *(float2*)p1 = make_float2(acc[mt][nt][2], acc[mt][nt][3]);
            }
    } else {
        int colbase = n0 + wn;
        int sector = colbase >> 10;
        int h = (colbase & 1023) >> 6;
        int d0 = 2 * (lane & 3);
        float scale = (sector == 0) ? 0.125f : 1.0f;
        __half* D = (sector == 0) ? Qh : (sector == 1) ? Kh : Vh;
#pragma unroll
        for (int mt = 0; mt < 2; mt++) {
            int mrow0 = m0 + wm + (lane >> 2) + mt * 16;
            int mrow1 = mrow0 + 8;
            size_t base0 = ((size_t)((mrow0 >> 11) * HH + h) * TT + (mrow0 & 2047)) * DHD + d0;
            size_t base1 = ((size_t)((mrow1 >> 11) * HH + h) * TT + (mrow1 & 2047)) * DHD + d0;
#pragma unroll
            for (int nt = 0; nt < 8; nt++) {
                *(__half2*)(D + base0 + nt * 8) =
                    __floats2half2_rn(acc[mt][nt][0] * scale, acc[mt][nt][1] * scale);
                *(__half2*)(D + base1 + nt * 8) =
                    __floats2half2_rn(acc[mt][nt][2] * scale, acc[mt][nt][3] * scale);
            }
        }
    }
}

// ---------------- flash attention (all single-term fp16) ----------------
__device__ __forceinline__ void flash_load_kv(
    uint32_t st, const __half* __restrict__ Kh, const __half* __restrict__ Vh,
    int bh, int k0, int tid)
{
#pragma unroll
    for (int i = 0; i < 2; i++) {
        int idx = tid + i * 256;
        int row = idx >> 3, c = idx & 7;
        size_t krow = ((size_t)bh * TT + k0 + row) * DHD;
        CP_ASYNC16(st + row * FROWB + c * 16,         (const char*)(Kh + krow) + c * 16);
        CP_ASYNC16(st + FTILE + row * FROWB + c * 16, (const char*)(Vh + krow) + c * 16);
    }
}

__global__ __launch_bounds__(256) void flash_mma(
    const __half* __restrict__ Qh, const __half* __restrict__ Kh,
    const __half* __restrict__ Vh, __half* __restrict__ AOh)
{
    extern __shared__ char smem[];
    uint32_t sb = smem_u32(smem);
    int tid = threadIdx.x, wid = tid >> 5, lane = tid & 31;
    int qblk = (TT / 128 - 1) - blockIdx.x;
    int bh = blockIdx.y;
    int q0 = qblk * 128;
    int wm = wid * 16;
    int nkt = 2 * qblk + 2;

    // ---- Q (hi only) into smem, consume to regs
#pragma unroll
    for (int i = 0; i < 4; i++) {
        int idx = tid + i * 256;           // 0..1023
        int row = idx >> 3, c = idx & 7;
        size_t qrow = ((size_t)bh * TT + q0 + row) * DHD;
        CP_ASYNC16(sb + row * FROWB + c * 16, (const char*)(Qh + qrow) + c * 16);
    }
    CP_COMMIT(); CP_WAIT(0);
    __syncthreads();
    uint32_t qaddr = sb + (uint32_t)(wm + (lane & 15)) * FROWB + (lane >> 4) * 16;
    uint32_t qf[4][4];
#pragma unroll
    for (int s = 0; s < 4; s++)
        ldsm4(qf[s], qaddr + s * 32);
    __syncthreads();

    float o[8][4];
#pragma unroll
    for (int j = 0; j < 8; j++)
#pragma unroll
        for (int k = 0; k < 4; k++) o[j][k] = 0.0f;
    float mrow0 = -1e30f, mrow1 = -1e30f, lrow0 = 0.0f, lrow1 = 0.0f;

    flash_load_kv(sb, Kh, Vh, bh, 0, tid);
    CP_COMMIT();
    flash_load_kv(sb + FSTAGE, Kh, Vh, bh, 64, tid);
    CP_COMMIT();

    uint32_t bpat = (uint32_t)((lane & 7) + ((lane >> 4) << 3)) * FROWB + ((lane >> 3) & 1) * 16;
    uint32_t vpat = (uint32_t)(lane & 15) * FROWB + ((lane >> 4) << 4);

    int sidx = 0;
    for (int kt = 0; kt < nkt; kt++) {
        uint32_t st = sb + sidx * FSTAGE;
        if (kt + 1 < nkt) { CP_WAIT(1); } else { CP_WAIT(0); }
        __syncthreads();
        if (kt + 2 < nkt) {
            int s2 = sidx + 2; if (s2 >= 3) s2 -= 3;
            flash_load_kv(sb + s2 * FSTAGE, Kh, Vh, bh, (kt + 2) * 64, tid);
            CP_COMMIT();
        }

        // ---- S = Q K^T (single term)
        float s[8][4];
#pragma unroll
        for (int j = 0; j < 8; j++)
#pragma unroll
            for (int k = 0; k < 4; k++) s[j][k] = 0.0f;
        uint32_t baseK = st + bpat;
#pragma unroll
        for (int ks = 0; ks < 4; ks++) {
            uint32_t koff = ks * 32;
            uint32_t kb[4][4];
#pragma unroll
            for (int np = 0; np < 4; np++)
                ldsm4(kb[np], baseK + np * 16 * FROWB + koff);
#pragma unroll
            for (int np = 0; np < 4; np++) {
                mma16816(s[np*2],   qf[ks], &kb[np][0]);
                mma16816(s[np*2+1], qf[ks], &kb[np][2]);
            }
        }

        // ---- causal mask
        int row0 = q0 + wm + (lane >> 2);
        if (kt * 64 + 63 > row0) {
#pragma unroll
            for (int j = 0; j < 8; j++) {
                int colb = kt * 64 + j * 8 + 2 * (lane & 3);
                if (colb     > row0)     s[j][0] = -1e30f;
                if (colb + 1 > row0)     s[j][1] = -1e30f;
                if (colb     > row0 + 8) s[j][2] = -1e30f;
                if (colb + 1 > row0 + 8) s[j][3] = -1e30f;
            }
        }

        // ---- online softmax
        float mx0 = -1e30f, mx1 = -1e30f;
#pragma unroll
        for (int j = 0; j < 8; j++) {
            mx0 = fmaxf(mx0, fmaxf(s[j][0], s[j][1]));
            mx1 = fmaxf(mx1, fmaxf(s[j][2], s[j][3]));
        }
        mx0 = fmaxf(mx0, __shfl_xor_sync(0xffffffff, mx0, 1));
        mx0 = fmaxf(mx0, __shfl_xor_sync(0xffffffff, mx0, 2));
        mx1 = fmaxf(mx1, __shfl_xor_sync(0xffffffff, mx1, 1));
        mx1 = fmaxf(mx1, __shfl_xor_sync(0xffffffff, mx1, 2));
        float mn0 = fmaxf(mrow0, mx0), mn1 = fmaxf(mrow1, mx1);
        float cr0 = __expf(mrow0 - mn0), cr1 = __expf(mrow1 - mn1);
        lrow0 *= cr0; lrow1 *= cr1;
#pragma unroll
        for (int j = 0; j < 8; j++) {
            o[j][0] *= cr0; o[j][1] *= cr0;
            o[j][2] *= cr1; o[j][3] *= cr1;
        }
        mrow0 = mn0; mrow1 = mn1;

        float ls0 = 0.0f, ls1 = 0.0f;
        uint32_t ph[8][2];
#pragma unroll
        for (int j = 0; j < 8; j++) {
            float p0 = __expf(s[j][0] - mn0), p1 = __expf(s[j][1] - mn0);
            float p2 = __expf(s[j][2] - mn1), p3 = __expf(s[j][3] - mn1);
            ls0 += p0 + p1; ls1 += p2 + p3;
            __half2 h0 = __floats2half2_rn(p0, p1);
            __half2 h1 = __floats2half2_rn(p2, p3);
            ph[j][0] = *(uint32_t*)&h0; ph[j][1] = *(uint32_t*)&h1;
        }
        ls0 += __shfl_xor_sync(0xffffffff, ls0, 1);
        ls0 += __shfl_xor_sync(0xffffffff, ls0, 2);
        ls1 += __shfl_xor_sync(0xffffffff, ls1, 1);
        ls1 += __shfl_xor_sync(0xffffffff, ls1, 2);
        lrow0 += ls0; lrow1 += ls1;

        // ---- O += P V (single P; V via ldmatrix.trans)
        uint32_t baseV = st + FTILE + vpat;
#pragma unroll
        for (int ks = 0; ks < 4; ks++) {
            uint32_t ath[4] = { ph[2*ks][0], ph[2*ks][1], ph[2*ks+1][0], ph[2*ks+1][1] };
            uint32_t roff = ks * 16 * FROWB;
            uint32_t vb[4][4];
#pragma unroll
            for (int np = 0; np < 4; np++)
                ldsm4t(vb[np], baseV + roff + np * 32);
#pragma unroll
            for (int np = 0; np < 4; np++) {
                mma16816(o[np*2],   ath, &vb[np][0]);
                mma16816(o[np*2+1], ath, &vb[np][2]);
            }
        }
        if (++sidx >= 3) sidx -= 3;
    }

    // ---- epilogue: normalize, fp16 AO
    float inv0 = 1.0f / lrow0, inv1 = 1.0f / lrow1;
    int b = bh >> 4, h = bh & 15;
    int r0 = q0 + wm + (lane >> 2);
    size_t base0 = (size_t)(b * TT + r0) * DD + h * DHD + 2 * (lane & 3);
    size_t base1 = base0 + (size_t)8 * DD;
#pragma unroll
    for (int j = 0; j < 8; j++) {
        *(__half2*)(AOh + base0 + j * 8) = __floats2half2_rn(o[j][0] * inv0, o[j][1] * inv0);
        *(__half2*)(AOh + base1 + j * 8) = __floats2half2_rn(o[j][2] * inv1, o[j][3] * inv1);
    }
}

// ---------------- launch ----------------
extern "C" void kernel_launch(void* const* d_in, const int* in_sizes, int n_in,
                              void* d_out, int out_size) {
    const float* x    = (const float*)d_in[0];
    const float* wq_w = (const float*)d_in[2];
    const float* wq_A = (const float*)d_in[3];
    const float* wq_B = (const float*)d_in[4];
    const float* wk_w = (const float*)d_in[5];
    const float* wv_w = (const float*)d_in[6];
    const float* wv_A = (const float*)d_in[7];
    const float* wv_B = (const float*)d_in[8];
    const float* wo_w = (const float*)d_in[9];
    float* out = (float*)d_out;

    static bool attr_set = false;
    if (!attr_set) {
        cudaFuncSetAttribute(gemm_ts<0>, cudaFuncAttributeMaxDynamicSharedMemorySize, SMEM_TOTAL);
        cudaFuncSetAttribute(gemm_ts<1>, cudaFuncAttributeMaxDynamicSharedMemorySize, SMEM_TOTAL);
        cudaFuncSetAttribute(flash_mma,  cudaFuncAttributeMaxDynamicSharedMemorySize, FSMEM);
        attr_set = true;
    }

    __half *Xh, *Wh, *WOh, *Qh, *Kh, *Vh, *AOh;
    cudaGetSymbolAddress((void**)&Xh,  g_Xh);
    cudaGetSymbolAddress((void**)&Wh,  g_Wh);
    cudaGetSymbolAddress((void**)&WOh, g_WOh);
    cudaGetSymbolAddress((void**)&Qh,  g_Qh);
    cudaGetSymbolAddress((void**)&Kh,  g_Kh);
    cudaGetSymbolAddress((void**)&Vh,  g_Vh);
    cudaGetSymbolAddress((void**)&AOh, g_AOh);

    to_half<<<(MTOT * DD) / 256, 256>>>(x, Xh, MTOT * DD);
    prep_wcat<<<(NQKV * DD) / 256, 256>>>(wq_w, wq_A, wq_B, wk_w, wv_w, wv_A, wv_B, Wh);
    to_half<<<(DD * DD) / 256, 256>>>(wo_w, WOh, DD * DD);

    gemm_ts<1><<<dim3(NQKV / TN, MTOT / TM), 256, SMEM_TOTAL>>>(
        Xh, Wh, nullptr, NQKV, Qh, Kh, Vh);

    flash_mma<<<dim3(TT / 128, BB * HH), 256, FSMEM>>>(Qh, Kh, Vh, AOh);

    gemm_ts<0><<<dim3(DD / TN, MTOT / TM), 256, SMEM_TOTAL>>>(
        AOh, WOh, out, DD, nullptr, nullptr, nullptr);
}

// round 9
// speedup vs baseline: 7.8293x; 1.0423x over previous
#include <cuda_runtime.h>
#include <cuda_fp16.h>
#include <cstdint>

#define DD    1024
#define TT    2048
#define BB    2
#define MTOT  4096
#define HH    16
#define DHD   64
#define RR    8
#define NQKV  3072

// ---- GEMM tiling: 128x128 CTA tile, 2 smem tiles/stage (A, B), 3 stages
#define TM 128
#define TN 128
#define KSTEP 32
#define NK (DD / KSTEP)              // 32
#define ROWB 80
#define TILE_BYTES (128 * ROWB)      // 10240
#define STAGE_BYTES (2 * TILE_BYTES) // 20480
#define NSTAGE 3
#define SMEM_TOTAL (NSTAGE * STAGE_BYTES) // 61440

// ---- flash tiling: K,V single fp16; 3 stages
#define FROWB 144
#define FTILE (64 * FROWB)          // 9216
#define FSTAGE (2 * FTILE)          // 18432  (Kh, Vh)
#define FSMEM (3 * FSTAGE)          // 55296

// Q scale: 1/sqrt(64) * log2(e)  (softmax done in exp2 domain)
#define QSCALE (0.125f * 1.44269504088896f)

// ---- scratch ----
__device__ __half g_Xh [MTOT * DD];
__device__ __half g_Wh [NQKV * DD];
__device__ __half g_WOh[DD * DD];
__device__ __half g_Qh [MTOT * DD];
__device__ __half g_Kh [MTOT * DD];
__device__ __half g_Vh [MTOT * DD];
__device__ __half g_AOh[MTOT * DD];

// ---------------- PTX helpers ----------------
__device__ __forceinline__ uint32_t smem_u32(const void* p) {
    uint32_t a;
    asm("{ .reg .u64 t; cvta.to.shared.u64 t, %1; cvt.u32.u64 %0, t; }" : "=r"(a) : "l"(p));
    return a;
}
#define CP_ASYNC16(dst, src) \
    asm volatile("cp.async.cg.shared.global [%0], [%1], 16;" :: "r"(dst), "l"(src))
#define CP_COMMIT()   asm volatile("cp.async.commit_group;" ::: "memory")
#define CP_WAIT(n)    asm volatile("cp.async.wait_group %0;" :: "n"(n) : "memory")

__device__ __forceinline__ void ldsm4(uint32_t* r, uint32_t addr) {
    asm volatile("ldmatrix.sync.aligned.m8n8.x4.shared.b16 {%0,%1,%2,%3}, [%4];"
                 : "=r"(r[0]), "=r"(r[1]), "=r"(r[2]), "=r"(r[3]) : "r"(addr));
}
__device__ __forceinline__ void ldsm4t(uint32_t* r, uint32_t addr) {
    asm volatile("ldmatrix.sync.aligned.m8n8.x4.trans.shared.b16 {%0,%1,%2,%3}, [%4];"
                 : "=r"(r[0]), "=r"(r[1]), "=r"(r[2]), "=r"(r[3]) : "r"(addr));
}
__device__ __forceinline__ void mma16816(float* c, const uint32_t* a, const uint32_t* b) {
    asm volatile("mma.sync.aligned.m16n8k16.row.col.f32.f16.f16.f32 "
                 "{%0,%1,%2,%3}, {%4,%5,%6,%7}, {%8,%9}, {%0,%1,%2,%3};"
                 : "+f"(c[0]), "+f"(c[1]), "+f"(c[2]), "+f"(c[3])
                 : "r"(a[0]), "r"(a[1]), "r"(a[2]), "r"(a[3]), "r"(b[0]), "r"(b[1]));
}

// ---------------- single fused prep kernel ----------------
// range 0: Xh (MTOT*DD), range 1: Wcat (NQKV*DD), range 2: WOh (DD*DD)
#define N_X  (MTOT * DD)
#define N_W  (NQKV * DD)
#define N_WO (DD * DD)
__global__ void prep_all(const float* __restrict__ x,
                         const float* __restrict__ wq, const float* __restrict__ qA,
                         const float* __restrict__ qB, const float* __restrict__ wk,
                         const float* __restrict__ wv, const float* __restrict__ vA,
                         const float* __restrict__ vB, const float* __restrict__ wo,
                         __half* __restrict__ Xh, __half* __restrict__ Wh,
                         __half* __restrict__ WOh) {
    int i = blockIdx.x * blockDim.x + threadIdx.x;
    if (i < N_X) {
        Xh[i] = __float2half_rn(x[i]);
        return;
    }
    i -= N_X;
    if (i < N_W) {
        int o = i / DD, c = i % DD;
        float v;
        if (o < 1024) {
            v = wq[o * DD + c];
#pragma unroll
            for (int r = 0; r < RR; r++) v += 2.0f * qB[o * RR + r] * qA[r * DD + c];
        } else if (o < 2048) {
            v = wk[(o - 1024) * DD + c];
        } else {
            int oo = o - 2048;
            v = wv[oo * DD + c];
#pragma unroll
            for (int r = 0; r < RR; r++) v += 2.0f * vB[oo * RR + r] * vA[r * DD + c];
        }
        Wh[i] = __float2half_rn(v);
        return;
    }
    i -= N_W;
    if (i < N_WO) WOh[i] = __float2half_rn(wo[i]);
}

// ---------------- single-term fp16 GEMM: C = A @ B^T ----------------
__device__ __forceinline__ void load_stage(
    uint32_t stage_base, const __half* __restrict__ A, const __half* __restrict__ B,
    int m0, int n0, int kc, int tid)
{
#pragma unroll
    for (int t = 0; t < 2; t++) {
        const __half* base = (t == 0 ? A : B) + (size_t)(t == 0 ? m0 : n0) * DD + kc * KSTEP;
        uint32_t dst_tile = stage_base + t * TILE_BYTES;
#pragma unroll
        for (int i = 0; i < 2; i++) {
            int idx = tid + i * 256;
            int row = idx >> 2, c = idx & 3;
            CP_ASYNC16(dst_tile + row * ROWB + c * 16,
                       (const char*)(base + (size_t)row * DD) + c * 16);
        }
    }
}

// MODE 0: fp32 C.  MODE 1: fused QKV epilogue (per-head fp16, Q scaled into exp2 domain)
template<int MODE>
__global__ __launch_bounds__(256, 2) void gemm_ts(
    const __half* __restrict__ A, const __half* __restrict__ B,
    float* __restrict__ C, int Ntot,
    __half* __restrict__ Qh, __half* __restrict__ Kh, __half* __restrict__ Vh)
{
    extern __shared__ char smem[];
    uint32_t sb = smem_u32(smem);
    int tid = threadIdx.x;
    int wid = tid >> 5, lane = tid & 31;
    int wm = (wid & 3) * 32;
    int wn = (wid >> 2) * 64;
    int m0 = blockIdx.y * TM, n0 = blockIdx.x * TN;

    uint32_t aoff = (uint32_t)(wm + (lane & 15)) * ROWB + (lane >> 4) * 16;
    uint32_t boff = (uint32_t)(wn + (lane & 7) + ((lane >> 4) << 3)) * ROWB
                  + ((lane >> 3) & 1) * 16;

    float acc[2][8][4];
#pragma unroll
    for (int i = 0; i < 2; i++)
#pragma unroll
        for (int j = 0; j < 8; j++)
#pragma unroll
            for (int k = 0; k < 4; k++) acc[i][j][k] = 0.0f;

    load_stage(sb, A, B, m0, n0, 0, tid);
    CP_COMMIT();
    load_stage(sb + STAGE_BYTES, A, B, m0, n0, 1, tid);
    CP_COMMIT();

    int sidx = 0;
    for (int c = 0; c < NK; c++) {
        uint32_t st = sb + sidx * STAGE_BYTES;
        if (c + 1 < NK) { CP_WAIT(1); } else { CP_WAIT(0); }
        __syncthreads();
        if (c + 2 < NK) {
            int s2 = sidx + 2; if (s2 >= NSTAGE) s2 -= NSTAGE;
            load_stage(sb + s2 * STAGE_BYTES, A, B, m0, n0, c + 2, tid);
            CP_COMMIT();
        }

        uint32_t baseA = st + aoff;
        uint32_t baseB = st + TILE_BYTES + boff;

#pragma unroll
        for (int kk = 0; kk < 2; kk++) {
            uint32_t koff = kk * 32;
            uint32_t a[2][4], b[4][4];
#pragma unroll
            for (int mt = 0; mt < 2; mt++)
                ldsm4(a[mt], baseA + mt * 16 * ROWB + koff);
#pragma unroll
            for (int np = 0; np < 4; np++)
                ldsm4(b[np], baseB + np * 16 * ROWB + koff);
#pragma unroll
            for (int mt = 0; mt < 2; mt++)
#pragma unroll
                for (int np = 0; np < 4; np++) {
                    mma16816(acc[mt][np*2],   a[mt], &b[np][0]);
                    mma16816(acc[mt][np*2+1], a[mt], &b[np][2]);
                }
        }
        if (++sidx >= NSTAGE) sidx -= NSTAGE;
    }

    if (MODE == 0) {
        int rbase = m0 + wm + (lane >> 2);
        int cbase = n0 + wn + 2 * (lane & 3);
#pragma unroll
        for (int mt = 0; mt < 2; mt++)
#pragma unroll
            for (int nt = 0; nt < 8; nt++) {
                float* p0 = C + (size_t)(rbase + mt * 16) * Ntot + cbase + nt * 8;
                float* p1 = C + (size_t)(rbase + mt * 16 + 8) * Ntot + cbase + nt * 8;
                *(float2*)p0 = make_float2(acc[mt][nt][0], acc[mt][nt][1]);
                *(float2*)p1 = make_float2(acc[mt][nt][2], acc[mt][nt][3]);
            }
    } else {
        int colbase = n0 + wn;
        int sector = colbase >> 10;
        int h = (colbase & 1023) >> 6;
        int d0 = 2 * (lane & 3);
        float scale = (sector == 0) ? QSCALE : 1.0f;
        __half* D = (sector == 0) ? Qh : (sector == 1) ? Kh : Vh;
#pragma unroll
        for (int mt = 0; mt < 2; mt++) {
            int mrow0 = m0 + wm + (lane >> 2) + mt * 16;
            int mrow1 = mrow0 + 8;
            size_t base0 = ((size_t)((mrow0 >> 11) * HH + h) * TT + (mrow0 & 2047)) * DHD + d0;
            size_t base1 = ((size_t)((mrow1 >> 11) * HH + h) * TT + (mrow1 & 2047)) * DHD + d0;
#pragma unroll
            for (int nt = 0; nt < 8; nt++) {
                *(__half2*)(D + base0 + nt * 8) =
                    __floats2half2_rn(acc[mt][nt][0] * scale, acc[mt][nt][1] * scale);
                *(__half2*)(D + base1 + nt * 8) =
                    __floats2half2_rn(acc[mt][nt][2] * scale, acc[mt][nt][3] * scale);
            }
        }
    }
}

// ---------------- flash attention (single-term fp16, exp2 softmax) ----------------
__device__ __forceinline__ void flash_load_kv(
    uint32_t st, const __half* __restrict__ Kh, const __half* __restrict__ Vh,
    int bh, int k0, int tid)
{
#pragma unroll
    for (int i = 0; i < 2; i++) {
        int idx = tid + i * 256;
        int row = idx >> 3, c = idx & 7;
        size_t krow = ((size_t)bh * TT + k0 + row) * DHD;
        CP_ASYNC16(st + row * FROWB + c * 16,         (const char*)(Kh + krow) + c * 16);
        CP_ASYNC16(st + FTILE + row * FROWB + c * 16, (const char*)(Vh + krow) + c * 16);
    }
}

__global__ __launch_bounds__(256, 2) void flash_mma(
    const __half* __restrict__ Qh, const __half* __restrict__ Kh,
    const __half* __restrict__ Vh, __half* __restrict__ AOh)
{
    extern __shared__ char smem[];
    uint32_t sb = smem_u32(smem);
    int tid = threadIdx.x, wid = tid >> 5, lane = tid & 31;
    int qblk = (TT / 128 - 1) - blockIdx.x;
    int bh = blockIdx.y;
    int q0 = qblk * 128;
    int wm = wid * 16;
    int nkt = 2 * qblk + 2;
    int wrow_max = q0 + wm + 15;     // highest q row this warp owns

    // ---- Q into smem, consume to regs
#pragma unroll
    for (int i = 0; i < 4; i++) {
        int idx = tid + i * 256;
        int row = idx >> 3, c = idx & 7;
        size_t qrow = ((size_t)bh * TT + q0 + row) * DHD;
        CP_ASYNC16(sb + row * FROWB + c * 16, (const char*)(Qh + qrow) + c * 16);
    }
    CP_COMMIT(); CP_WAIT(0);
    __syncthreads();
    uint32_t qaddr = sb + (uint32_t)(wm + (lane & 15)) * FROWB + (lane >> 4) * 16;
    uint32_t qf[4][4];
#pragma unroll
    for (int s = 0; s < 4; s++)
        ldsm4(qf[s], qaddr + s * 32);
    __syncthreads();

    float o[8][4];
#pragma unroll
    for (int j = 0; j < 8; j++)
#pragma unroll
        for (int k = 0; k < 4; k++) o[j][k] = 0.0f;
    float mrow0 = -1e30f, mrow1 = -1e30f, lrow0 = 0.0f, lrow1 = 0.0f;

    flash_load_kv(sb, Kh, Vh, bh, 0, tid);
    CP_COMMIT();
    flash_load_kv(sb + FSTAGE, Kh, Vh, bh, 64, tid);
    CP_COMMIT();

    uint32_t bpat = (uint32_t)((lane & 7) + ((lane >> 4) << 3)) * FROWB + ((lane >> 3) & 1) * 16;
    uint32_t vpat = (uint32_t)(lane & 15) * FROWB + ((lane >> 4) << 4);

    int sidx = 0;
    for (int kt = 0; kt < nkt; kt++) {
        uint32_t st = sb + sidx * FSTAGE;
        if (kt + 1 < nkt) { CP_WAIT(1); } else { CP_WAIT(0); }
        __syncthreads();
        if (kt + 2 < nkt) {
            int s2 = sidx + 2; if (s2 >= 3) s2 -= 3;
            flash_load_kv(sb + s2 * FSTAGE, Kh, Vh, bh, (kt + 2) * 64, tid);
            CP_COMMIT();
        }

        // warp-level skip: this k-tile entirely above this warp's diagonal
        if (kt * 64 <= wrow_max) {
            // ---- S = Q K^T
            float s[8][4];
#pragma unroll
            for (int j = 0; j < 8; j++)
#pragma unroll
                for (int k = 0; k < 4; k++) s[j][k] = 0.0f;
            uint32_t baseK = st + bpat;
#pragma unroll
            for (int ks = 0; ks < 4; ks++) {
                uint32_t koff = ks * 32;
                uint32_t kb[4][4];
#pragma unroll
                for (int np = 0; np < 4; np++)
                    ldsm4(kb[np], baseK + np * 16 * FROWB + koff);
#pragma unroll
                for (int np = 0; np < 4; np++) {
                    mma16816(s[np*2],   qf[ks], &kb[np][0]);
                    mma16816(s[np*2+1], qf[ks], &kb[np][2]);
                }
            }

            // ---- causal mask
            int row0 = q0 + wm + (lane >> 2);
            if (kt * 64 + 63 > row0) {
#pragma unroll
                for (int j = 0; j < 8; j++) {
                    int colb = kt * 64 + j * 8 + 2 * (lane & 3);
                    if (colb     > row0)     s[j][0] = -1e30f;
                    if (colb + 1 > row0)     s[j][1] = -1e30f;
                    if (colb     > row0 + 8) s[j][2] = -1e30f;
                    if (colb + 1 > row0 + 8) s[j][3] = -1e30f;
                }
            }

            // ---- online softmax (exp2 domain)
            float mx0 = -1e30f, mx1 = -1e30f;
#pragma unroll
            for (int j = 0; j < 8; j++) {
                mx0 = fmaxf(mx0, fmaxf(s[j][0], s[j][1]));
                mx1 = fmaxf(mx1, fmaxf(s[j][2], s[j][3]));
            }
            mx0 = fmaxf(mx0, __shfl_xor_sync(0xffffffff, mx0, 1));
            mx0 = fmaxf(mx0, __shfl_xor_sync(0xffffffff, mx0, 2));
            mx1 = fmaxf(mx1, __shfl_xor_sync(0xffffffff, mx1, 1));
            mx1 = fmaxf(mx1, __shfl_xor_sync(0xffffffff, mx1, 2));
            float mn0 = fmaxf(mrow0, mx0), mn1 = fmaxf(mrow1, mx1);
            float cr0 = exp2f(mrow0 - mn0), cr1 = exp2f(mrow1 - mn1);
            lrow0 *= cr0; lrow1 *= cr1;
#pragma unroll
            for (int j = 0; j < 8; j++) {
                o[j][0] *= cr0; o[j][1] *= cr0;
                o[j][2] *= cr1; o[j][3] *= cr1;
            }
            mrow0 = mn0; mrow1 = mn1;

            float ls0 = 0.0f, ls1 = 0.0f;
            uint32_t ph[8][2];
#pragma unroll
            for (int j = 0; j < 8; j++) {
                float p0 = exp2f(s[j][0] - mn0), p1 = exp2f(s[j][1] - mn0);
                float p2 = exp2f(s[j][2] - mn1), p3 = exp2f(s[j][3] - mn1);
                ls0 += p0 + p1; ls1 += p2 + p3;
                __half2 h0 = __floats2half2_rn(p0, p1);
                __half2 h1 = __floats2half2_rn(p2, p3);
                ph[j][0] = *(uint32_t*)&h0; ph[j][1] = *(uint32_t*)&h1;
            }
            ls0 += __shfl_xor_sync(0xffffffff, ls0, 1);
            ls0 += __shfl_xor_sync(0xffffffff, ls0, 2);
            ls1 += __shfl_xor_sync(0xffffffff, ls1, 1);
            ls1 += __shfl_xor_sync(0xffffffff, ls1, 2);
            lrow0 += ls0; lrow1 += ls1;

            // ---- O += P V
            uint32_t baseV = st + FTILE + vpat;
#pragma unroll
            for (int ks = 0; ks < 4; ks++) {
                uint32_t ath[4] = { ph[2*ks][0], ph[2*ks][1], ph[2*ks+1][0], ph[2*ks+1][1] };
                uint32_t roff = ks * 16 * FROWB;
                uint32_t vb[4][4];
#pragma unroll
                for (int np = 0; np < 4; np++)
                    ldsm4t(vb[np], baseV + roff + np * 32);
#pragma unroll
                for (int np = 0; np < 4; np++) {
                    mma16816(o[np*2],   ath, &vb[np][0]);
                    mma16816(o[np*2+1], ath, &vb[np][2]);
                }
            }
        }
        if (++sidx >= 3) sidx -= 3;
    }

    // ---- epilogue: normalize, fp16 AO
    float inv0 = 1.0f / lrow0, inv1 = 1.0f / lrow1;
    int b = bh >> 4, h = bh & 15;
    int r0 = q0 + wm + (lane >> 2);
    size_t base0 = (size_t)(b * TT + r0) * DD + h * DHD + 2 * (lane & 3);
    size_t base1 = base0 + (size_t)8 * DD;
#pragma unroll
    for (int j = 0; j < 8; j++) {
        *(__half2*)(AOh + base0 + j * 8) = __floats2half2_rn(o[j][0] * inv0, o[j][1] * inv0);
        *(__half2*)(AOh + base1 + j * 8) = __floats2half2_rn(o[j][2] * inv1, o[j][3] * inv1);
    }
}

// ---------------- launch ----------------
extern "C" void kernel_launch(void* const* d_in, const int* in_sizes, int n_in,
                              void* d_out, int out_size) {
    const float* x    = (const float*)d_in[0];
    const float* wq_w = (const float*)d_in[2];
    const float* wq_A = (const float*)d_in[3];
    const float* wq_B = (const float*)d_in[4];
    const float* wk_w = (const float*)d_in[5];
    const float* wv_w = (const float*)d_in[6];
    const float* wv_A = (const float*)d_in[7];
    const float* wv_B = (const float*)d_in[8];
    const float* wo_w = (const float*)d_in[9];
    float* out = (float*)d_out;

    static bool attr_set = false;
    if (!attr_set) {
        cudaFuncSetAttribute(gemm_ts<0>, cudaFuncAttributeMaxDynamicSharedMemorySize, SMEM_TOTAL);
        cudaFuncSetAttribute(gemm_ts<1>, cudaFuncAttributeMaxDynamicSharedMemorySize, SMEM_TOTAL);
        cudaFuncSetAttribute(flash_mma,  cudaFuncAttributeMaxDynamicSharedMemorySize, FSMEM);
        attr_set = true;
    }

    __half *Xh, *Wh, *WOh, *Qh, *Kh, *Vh, *AOh;
    cudaGetSymbolAddress((void**)&Xh,  g_Xh);
    cudaGetSymbolAddress((void**)&Wh,  g_Wh);
    cudaGetSymbolAddress((void**)&WOh, g_WOh);
    cudaGetSymbolAddress((void**)&Qh,  g_Qh);
    cudaGetSymbolAddress((void**)&Kh,  g_Kh);
    cudaGetSymbolAddress((void**)&Vh,  g_Vh);
    cudaGetSymbolAddress((void**)&AOh, g_AOh);

    prep_all<<<(N_X + N_W + N_WO) / 256, 256>>>(
        x, wq_w, wq_A, wq_B, wk_w, wv_w, wv_A, wv_B, wo_w, Xh, Wh, WOh);

    gemm_ts<1><<<dim3(NQKV / TN, MTOT / TM), 256, SMEM_TOTAL>>>(
        Xh, Wh, nullptr, NQKV, Qh, Kh, Vh);

    flash_mma<<<dim3(TT / 128, BB * HH), 256, FSMEM>>>(Qh, Kh, Vh, AOh);

    gemm_ts<0><<<dim3(DD / TN, MTOT / TM), 256, SMEM_TOTAL>>>(
        AOh, WOh, out, DD, nullptr, nullptr, nullptr);
}